// round 14
// baseline (speedup 1.0000x reference)
#include <cuda_runtime.h>
#include <math.h>

// ---------------- problem constants ----------------
#define BB   2
#define NTOK 577
#define DIMM 512
#define HH   8
#define DHH  64
#define NCC  145
#define NSB  10
#define KSEL 4
#define SWIN 32
#define MLPD 2048
#define NCLS 1000
#define BN   (BB*NTOK)    // 1154
#define QCA  12
#define NQBA 49
#define CM   (BB*HH*NCC)  // 2320
#define QT   16
#define NQT  37
#define PARTSZ (16*CM*64)

#define ACT_NONE 0
#define ACT_GELU 1
#define ACT_SIG  2

// ---------------- device scratch ----------------
__device__ float g_x   [BN*DIMM];
__device__ float g_h   [BN*DIMM];
__device__ float g_q   [BN*DIMM];
__device__ float g_k   [BN*DIMM];
__device__ float g_v   [BN*DIMM];
__device__ float g_gate[BN*24];
__device__ float g_ckcv[2*CM*DHH];
__device__ float g_outc[BB*HH*NTOK*DHH];
__device__ int   g_selb[BB*HH*NTOK*KSEL];
__device__ float g_attn[BN*DIMM];
__device__ float g_mlp [BN*MLPD];
__device__ float g_part[PARTSZ];
__device__ float g_hb  [BB*DIMM];

// ---------------- helpers ----------------
__device__ __forceinline__ float gelu_tanh(float x) {
    float x3 = x * x * x;
    return 0.5f * x * (1.0f + tanhf(0.7978845608028654f * (x + 0.044715f * x3)));
}

__device__ __forceinline__ float blk_sum256(float v, float* sred) {
    #pragma unroll
    for (int o = 16; o; o >>= 1) v += __shfl_xor_sync(0xffffffffu, v, o);
    __syncthreads();
    if ((threadIdx.x & 31) == 0) sred[threadIdx.x >> 5] = v;
    __syncthreads();
    float r = sred[0];
    #pragma unroll
    for (int w = 1; w < 8; w++) r += sred[w];
    return r;
}
__device__ __forceinline__ float blk_sum128(float v, float* sred) {
    #pragma unroll
    for (int o = 16; o; o >>= 1) v += __shfl_xor_sync(0xffffffffu, v, o);
    __syncthreads();
    if ((threadIdx.x & 31) == 0) sred[threadIdx.x >> 5] = v;
    __syncthreads();
    return sred[0] + sred[1] + sred[2] + sred[3];
}

// ---------------- patch embed + cls + pos ----------------
__global__ void patch_embed_kernel(const float* __restrict__ img,
                                   const float* __restrict__ pw,
                                   const float* __restrict__ pb,
                                   const float* __restrict__ pos,
                                   const float* __restrict__ cls,
                                   float* __restrict__ x) {
    int t = blockIdx.x % NTOK;
    int b = blockIdx.x / NTOK;
    for (int d = threadIdx.x; d < DIMM; d += blockDim.x) {
        float v;
        if (t == 0) {
            v = cls[d];
        } else {
            int p = t - 1;
            int ii = p / 24, jj = p % 24;
            v = pb[d];
            #pragma unroll
            for (int c = 0; c < 3; c++)
                v += img[((b * 3 + c) * 24 + ii) * 24 + jj] * pw[c * DIMM + d];
        }
        x[((size_t)(b * NTOK + t)) * DIMM + d] = v + pos[(size_t)t * DIMM + d];
    }
}

// ---------------- layernorm (standalone) ----------------
__global__ __launch_bounds__(256) void ln_kernel(const float* __restrict__ in, long strideIn,
                          float* __restrict__ out,
                          const float* __restrict__ g, const float* __restrict__ bb) {
    __shared__ float sred[8];
    int r = blockIdx.x;
    const float* row = in + (size_t)r * strideIn;
    int t = threadIdx.x;
    float a0 = row[t], a1 = row[t + 256];
    float mean = blk_sum256(a0 + a1, sred) * (1.0f / 512.0f);
    float d0 = a0 - mean, d1 = a1 - mean;
    __syncthreads();
    float var = blk_sum256(d0 * d0 + d1 * d1, sred) * (1.0f / 512.0f);
    float inv = rsqrtf(var + 1e-5f);
    out[(size_t)r * DIMM + t]       = d0 * inv * g[t] + bb[t];
    out[(size_t)r * DIMM + t + 256] = d1 * inv * g[t + 256] + bb[t + 256];
}

// ---------------- SGEMM core A: 64x64 tile, 4x4/thread ----------------
__device__ __forceinline__ void gemm_core(
    const float* __restrict__ A, const float* __restrict__ W,
    const float* __restrict__ bias, const float* __restrict__ res,
    float* __restrict__ C, float* __restrict__ part,
    int M, int Nn, int K, int act, int row0, int col0, int k0, int kLen)
{
    __shared__ __align__(16) float As[2][16][68];
    __shared__ __align__(16) float Bs[2][16][64];
    int tid = threadIdx.x;
    int tx = tid & 15, ty = tid >> 4;

    int am  = tid >> 2;
    int akq = tid & 3;
    int arow = row0 + am;
    const float* Aptr = (arow < M) ? (A + (size_t)arow * K + k0 + akq * 4) : (const float*)0;
    int bkk = tid >> 4;
    int bnq = tid & 15;
    int bcol = col0 + bnq * 4;
    const float* Wptr = W + (size_t)(k0 + bkk) * Nn + bcol;
    bool bfull = (bcol + 3 < Nn);
    bool bany  = (bcol < Nn);

    float4 a4, b4;
    if (Aptr) a4 = *(const float4*)(Aptr);
    else      a4 = make_float4(0.f, 0.f, 0.f, 0.f);
    if (bfull) b4 = *(const float4*)(Wptr);
    else {
        b4 = make_float4(0.f, 0.f, 0.f, 0.f);
        if (bany) {
            b4.x = Wptr[0];
            if (bcol + 1 < Nn) b4.y = Wptr[1];
            if (bcol + 2 < Nn) b4.z = Wptr[2];
        }
    }
    As[0][akq * 4 + 0][am] = a4.x;
    As[0][akq * 4 + 1][am] = a4.y;
    As[0][akq * 4 + 2][am] = a4.z;
    As[0][akq * 4 + 3][am] = a4.w;
    *(float4*)&Bs[0][bkk][bnq * 4] = b4;
    __syncthreads();

    float acc[4][4];
    #pragma unroll
    for (int i = 0; i < 4; i++)
        #pragma unroll
        for (int j = 0; j < 4; j++) acc[i][j] = 0.f;

    int steps = kLen >> 4;
    for (int ks = 0; ks < steps; ks++) {
        int cur = ks & 1;
        bool hn = (ks + 1 < steps);
        if (hn) {
            int kk0 = (ks + 1) * 16;
            if (Aptr) a4 = *(const float4*)(Aptr + kk0);
            else      a4 = make_float4(0.f, 0.f, 0.f, 0.f);
            if (bfull) b4 = *(const float4*)(Wptr + (size_t)kk0 * Nn);
            else {
                b4 = make_float4(0.f, 0.f, 0.f, 0.f);
                if (bany) {
                    const float* p = Wptr + (size_t)kk0 * Nn;
                    b4.x = p[0];
                    if (bcol + 1 < Nn) b4.y = p[1];
                    if (bcol + 2 < Nn) b4.z = p[2];
                }
            }
        }
        #pragma unroll
        for (int kk = 0; kk < 16; kk++) {
            float4 av = *(const float4*)&As[cur][kk][ty * 4];
            float4 bv = *(const float4*)&Bs[cur][kk][tx * 4];
            acc[0][0] += av.x * bv.x; acc[0][1] += av.x * bv.y; acc[0][2] += av.x * bv.z; acc[0][3] += av.x * bv.w;
            acc[1][0] += av.y * bv.x; acc[1][1] += av.y * bv.y; acc[1][2] += av.y * bv.z; acc[1][3] += av.y * bv.w;
            acc[2][0] += av.z * bv.x; acc[2][1] += av.z * bv.y; acc[2][2] += av.z * bv.z; acc[2][3] += av.z * bv.w;
            acc[3][0] += av.w * bv.x; acc[3][1] += av.w * bv.y; acc[3][2] += av.w * bv.z; acc[3][3] += av.w * bv.w;
        }
        if (hn) {
            int nxt = cur ^ 1;
            As[nxt][akq * 4 + 0][am] = a4.x;
            As[nxt][akq * 4 + 1][am] = a4.y;
            As[nxt][akq * 4 + 2][am] = a4.z;
            As[nxt][akq * 4 + 3][am] = a4.w;
            *(float4*)&Bs[nxt][bkk][bnq * 4] = b4;
            __syncthreads();
        }
    }
    #pragma unroll
    for (int i = 0; i < 4; i++) {
        int r = row0 + ty * 4 + i;
        if (r >= M) continue;
        #pragma unroll
        for (int j = 0; j < 4; j++) {
            int c = col0 + tx * 4 + j;
            if (c >= Nn) continue;
            float v = acc[i][j];
            size_t off = (size_t)r * Nn + c;
            if (part) {
                part[off] = v;
            } else {
                if (bias) v += bias[c];
                if (act == ACT_GELU) v = gelu_tanh(v);
                else if (act == ACT_SIG) v = 1.0f / (1.0f + expf(-v));
                if (res) v += res[off];
                C[off] = v;
            }
        }
    }
}

// ---------------- SGEMM core B: 64x128 tile, 4x8/thread ----------------
__device__ __forceinline__ void gemmW_core(
    const float* __restrict__ A, const float* __restrict__ W,
    const float* __restrict__ bias, const float* __restrict__ res,
    float* __restrict__ C, float* __restrict__ part,
    int M, int Nn, int K, int act, int row0, int col0, int k0, int kLen)
{
    __shared__ __align__(16) float As[2][16][68];
    __shared__ __align__(16) float Bs[2][16][128];
    int tid = threadIdx.x;
    int tx = tid & 15, ty = tid >> 4;

    int am  = tid >> 2;
    int akq = tid & 3;
    int arow = row0 + am;
    const float* Aptr = (arow < M) ? (A + (size_t)arow * K + k0 + akq * 4) : (const float*)0;
    int bkk = tid >> 4;
    int bnq = tid & 15;
    const float* Wptr = W + (size_t)(k0 + bkk) * Nn + col0 + bnq * 4;

    float4 a4, b4a, b4b;
    if (Aptr) a4 = *(const float4*)(Aptr);
    else      a4 = make_float4(0.f, 0.f, 0.f, 0.f);
    b4a = *(const float4*)(Wptr);
    b4b = *(const float4*)(Wptr + 64);
    As[0][akq * 4 + 0][am] = a4.x;
    As[0][akq * 4 + 1][am] = a4.y;
    As[0][akq * 4 + 2][am] = a4.z;
    As[0][akq * 4 + 3][am] = a4.w;
    *(float4*)&Bs[0][bkk][bnq * 4]      = b4a;
    *(float4*)&Bs[0][bkk][64 + bnq * 4] = b4b;
    __syncthreads();

    float acc[4][8];
    #pragma unroll
    for (int i = 0; i < 4; i++)
        #pragma unroll
        for (int j = 0; j < 8; j++) acc[i][j] = 0.f;

    int steps = kLen >> 4;
    for (int ks = 0; ks < steps; ks++) {
        int cur = ks & 1;
        bool hn = (ks + 1 < steps);
        if (hn) {
            int kk0 = (ks + 1) * 16;
            if (Aptr) a4 = *(const float4*)(Aptr + kk0);
            else      a4 = make_float4(0.f, 0.f, 0.f, 0.f);
            const float* p = Wptr + (size_t)kk0 * Nn;
            b4a = *(const float4*)(p);
            b4b = *(const float4*)(p + 64);
        }
        #pragma unroll
        for (int kk = 0; kk < 16; kk++) {
            float4 av = *(const float4*)&As[cur][kk][ty * 4];
            float4 bv0 = *(const float4*)&Bs[cur][kk][tx * 4];
            float4 bv1 = *(const float4*)&Bs[cur][kk][64 + tx * 4];
            float a0 = av.x, a1 = av.y, a2 = av.z, a3 = av.w;
            acc[0][0] += a0 * bv0.x; acc[0][1] += a0 * bv0.y; acc[0][2] += a0 * bv0.z; acc[0][3] += a0 * bv0.w;
            acc[0][4] += a0 * bv1.x; acc[0][5] += a0 * bv1.y; acc[0][6] += a0 * bv1.z; acc[0][7] += a0 * bv1.w;
            acc[1][0] += a1 * bv0.x; acc[1][1] += a1 * bv0.y; acc[1][2] += a1 * bv0.z; acc[1][3] += a1 * bv0.w;
            acc[1][4] += a1 * bv1.x; acc[1][5] += a1 * bv1.y; acc[1][6] += a1 * bv1.z; acc[1][7] += a1 * bv1.w;
            acc[2][0] += a2 * bv0.x; acc[2][1] += a2 * bv0.y; acc[2][2] += a2 * bv0.z; acc[2][3] += a2 * bv0.w;
            acc[2][4] += a2 * bv1.x; acc[2][5] += a2 * bv1.y; acc[2][6] += a2 * bv1.z; acc[2][7] += a2 * bv1.w;
            acc[3][0] += a3 * bv0.x; acc[3][1] += a3 * bv0.y; acc[3][2] += a3 * bv0.z; acc[3][3] += a3 * bv0.w;
            acc[3][4] += a3 * bv1.x; acc[3][5] += a3 * bv1.y; acc[3][6] += a3 * bv1.z; acc[3][7] += a3 * bv1.w;
        }
        if (hn) {
            int nxt = cur ^ 1;
            As[nxt][akq * 4 + 0][am] = a4.x;
            As[nxt][akq * 4 + 1][am] = a4.y;
            As[nxt][akq * 4 + 2][am] = a4.z;
            As[nxt][akq * 4 + 3][am] = a4.w;
            *(float4*)&Bs[nxt][bkk][bnq * 4]      = b4a;
            *(float4*)&Bs[nxt][bkk][64 + bnq * 4] = b4b;
            __syncthreads();
        }
    }
    #pragma unroll
    for (int i = 0; i < 4; i++) {
        int r = row0 + ty * 4 + i;
        if (r >= M) continue;
        #pragma unroll
        for (int half = 0; half < 2; half++) {
            int c = col0 + half * 64 + tx * 4;
            size_t off = (size_t)r * Nn + c;
            float4 v;
            v.x = acc[i][half * 4 + 0]; v.y = acc[i][half * 4 + 1];
            v.z = acc[i][half * 4 + 2]; v.w = acc[i][half * 4 + 3];
            if (part) {
                *(float4*)(part + off) = v;
            } else {
                if (bias) {
                    v.x += bias[c]; v.y += bias[c + 1];
                    v.z += bias[c + 2]; v.w += bias[c + 3];
                }
                if (act == ACT_GELU) {
                    v.x = gelu_tanh(v.x); v.y = gelu_tanh(v.y);
                    v.z = gelu_tanh(v.z); v.w = gelu_tanh(v.w);
                }
                if (res) {
                    float4 r4 = *(const float4*)(res + off);
                    v.x += r4.x; v.y += r4.y; v.z += r4.z; v.w += r4.w;
                }
                *(float4*)(C + off) = v;
            }
        }
    }
}

__global__ __launch_bounds__(256) void gemmW_split_kernel(
    const float* __restrict__ A, const float* __restrict__ W,
    float* __restrict__ part, int M, int Nn, int K)
{
    int chunk = K / gridDim.z;
    float* p = part + (size_t)blockIdx.z * M * Nn;
    gemmW_core(A, W, (const float*)0, (const float*)0, (float*)0, p,
               M, Nn, K, ACT_NONE,
               blockIdx.y * 64, blockIdx.x * 128, blockIdx.z * chunk, chunk);
}

// ---------------- SGEMM core C: 128x128 tile, 8x8/thread (ff1) ----------------
// Requires Nn % 128 == 0, K % 8 == 0. Row guards on M.
__global__ __launch_bounds__(256) void gemm128_kernel(
    const float* __restrict__ A, const float* __restrict__ W,
    const float* __restrict__ bias, float* __restrict__ C,
    int M, int N, int K)
{
    __shared__ __align__(16) float As[2][8][132];
    __shared__ __align__(16) float Bs[2][8][128];
    int tid = threadIdx.x;
    int tx = tid & 15, ty = tid >> 4;
    int row0 = blockIdx.y * 128, col0 = blockIdx.x * 128;

    int aRow = tid >> 1;
    int aK = (tid & 1) * 4;
    int arow_g = row0 + aRow; if (arow_g >= M) arow_g = M - 1;
    const float* Ap = A + (size_t)arow_g * K + aK;

    int bK = tid >> 5;
    int bNq = (tid & 31) * 4;
    const float* Wp = W + (size_t)bK * N + col0 + bNq;

    float4 aReg = *(const float4*)Ap;
    float4 bReg = *(const float4*)Wp;

    float acc[2][2][4][4];
    #pragma unroll
    for (int p = 0; p < 2; p++)
        #pragma unroll
        for (int qq = 0; qq < 2; qq++)
            #pragma unroll
            for (int i = 0; i < 4; i++)
                #pragma unroll
                for (int j = 0; j < 4; j++) acc[p][qq][i][j] = 0.f;

    As[0][aK + 0][aRow] = aReg.x;
    As[0][aK + 1][aRow] = aReg.y;
    As[0][aK + 2][aRow] = aReg.z;
    As[0][aK + 3][aRow] = aReg.w;
    *(float4*)&Bs[0][bK][bNq] = bReg;
    __syncthreads();

    int steps = K >> 3;
    for (int s = 0; s < steps; s++) {
        int cur = s & 1;
        bool hn = (s + 1 < steps);
        if (hn) {
            aReg = *(const float4*)(Ap + (s + 1) * 8);
            bReg = *(const float4*)(Wp + (size_t)(s + 1) * 8 * N);
        }
        #pragma unroll
        for (int kk = 0; kk < 8; kk++) {
            float4 a0 = *(const float4*)&As[cur][kk][ty * 4];
            float4 a1 = *(const float4*)&As[cur][kk][64 + ty * 4];
            float4 b0 = *(const float4*)&Bs[cur][kk][tx * 4];
            float4 b1 = *(const float4*)&Bs[cur][kk][64 + tx * 4];
            float av0[4] = {a0.x, a0.y, a0.z, a0.w};
            float av1[4] = {a1.x, a1.y, a1.z, a1.w};
            float bv0[4] = {b0.x, b0.y, b0.z, b0.w};
            float bv1[4] = {b1.x, b1.y, b1.z, b1.w};
            #pragma unroll
            for (int i = 0; i < 4; i++)
                #pragma unroll
                for (int j = 0; j < 4; j++) {
                    acc[0][0][i][j] += av0[i] * bv0[j];
                    acc[0][1][i][j] += av0[i] * bv1[j];
                    acc[1][0][i][j] += av1[i] * bv0[j];
                    acc[1][1][i][j] += av1[i] * bv1[j];
                }
        }
        if (hn) {
            int nxt = cur ^ 1;
            As[nxt][aK + 0][aRow] = aReg.x;
            As[nxt][aK + 1][aRow] = aReg.y;
            As[nxt][aK + 2][aRow] = aReg.z;
            As[nxt][aK + 3][aRow] = aReg.w;
            *(float4*)&Bs[nxt][bK][bNq] = bReg;
            __syncthreads();
        }
    }

    #pragma unroll
    for (int qy = 0; qy < 2; qy++) {
        #pragma unroll
        for (int i = 0; i < 4; i++) {
            int r = row0 + qy * 64 + ty * 4 + i;
            if (r >= M) continue;
            #pragma unroll
            for (int qx = 0; qx < 2; qx++) {
                int c = col0 + qx * 64 + tx * 4;
                float4 v;
                v.x = acc[qy][qx][i][0]; v.y = acc[qy][qx][i][1];
                v.z = acc[qy][qx][i][2]; v.w = acc[qy][qx][i][3];
                v.x = gelu_tanh(v.x + bias[c]);
                v.y = gelu_tanh(v.y + bias[c + 1]);
                v.z = gelu_tanh(v.z + bias[c + 2]);
                v.w = gelu_tanh(v.w + bias[c + 3]);
                *(float4*)(C + (size_t)r * N + c) = v;
            }
        }
    }
}

// fused QKV (64x128 core) + gate (64x64 core)
__global__ __launch_bounds__(256) void qkvgW_kernel(
    const float* __restrict__ h,
    const float* __restrict__ Wq, const float* __restrict__ Wk,
    const float* __restrict__ Wv, const float* __restrict__ Wg,
    float* __restrict__ q, float* __restrict__ k,
    float* __restrict__ v, float* __restrict__ gate)
{
    int bx = blockIdx.x;
    if (bx < 12) {
        int sel = bx >> 2;
        const float* W; float* C;
        if (sel == 0)      { W = Wq; C = q; }
        else if (sel == 1) { W = Wk; C = k; }
        else               { W = Wv; C = v; }
        gemmW_core(h, W, (const float*)0, (const float*)0, C, (float*)0,
                   BN, DIMM, DIMM, ACT_NONE, blockIdx.y * 64, (bx & 3) * 128, 0, DIMM);
    } else {
        gemm_core(h, Wg, (const float*)0, (const float*)0, gate, (float*)0,
                  BN, 24, DIMM, ACT_SIG, blockIdx.y * 64, 0, 0, DIMM);
    }
}

// ---------------- fused split-K reduce + residual + LayerNorm ----------------
__global__ __launch_bounds__(128) void reduce_ln_kernel(
    const float* __restrict__ part, const float* __restrict__ bias,
    const float* __restrict__ res, float* __restrict__ x,
    const float* __restrict__ gamma, const float* __restrict__ beta,
    float* __restrict__ h, int S)
{
    __shared__ float sred[4];
    int r = blockIdx.x;
    int t = threadIdx.x;
    int c = t * 4;
    size_t off = (size_t)r * DIMM + c;
    size_t stride = (size_t)BN * DIMM;
    float4 s = *(const float4*)(part + off);
    for (int i = 1; i < S; i++) {
        float4 p = *(const float4*)(part + (size_t)i * stride + off);
        s.x += p.x; s.y += p.y; s.z += p.z; s.w += p.w;
    }
    if (bias) {
        s.x += bias[c]; s.y += bias[c + 1]; s.z += bias[c + 2]; s.w += bias[c + 3];
    }
    if (res) {
        float4 r4 = *(const float4*)(res + off);
        s.x += r4.x; s.y += r4.y; s.z += r4.z; s.w += r4.w;
    }
    *(float4*)(x + off) = s;
    if (!gamma) return;
    float mean = blk_sum128(s.x + s.y + s.z + s.w, sred) * (1.0f / 512.0f);
    float d0 = s.x - mean, d1 = s.y - mean, d2 = s.z - mean, d3 = s.w - mean;
    __syncthreads();
    float var = blk_sum128(d0 * d0 + d1 * d1 + d2 * d2 + d3 * d3, sred) * (1.0f / 512.0f);
    float inv = rsqrtf(var + 1e-5f);
    float4 o;
    o.x = d0 * inv * gamma[c]     + beta[c];
    o.y = d1 * inv * gamma[c + 1] + beta[c + 1];
    o.z = d2 * inv * gamma[c + 2] + beta[c + 2];
    o.w = d3 * inv * gamma[c + 3] + beta[c + 3];
    *(float4*)(h + off) = o;
}

// generic split-K reduce (compress path: both ck and cv in one launch)
__global__ __launch_bounds__(256) void reduce4_kernel(
    const float* __restrict__ part, float* __restrict__ C, int MN4, int S)
{
    int idx = blockIdx.x * 256 + threadIdx.x;
    if (idx >= MN4) return;
    size_t off = (size_t)idx * 4;
    size_t stride = (size_t)MN4 * 4;
    float4 s = *(const float4*)(part + off);
    for (int t = 1; t < S; t++) {
        float4 p = *(const float4*)(part + (size_t)t * stride + off);
        s.x += p.x; s.y += p.y; s.z += p.z; s.w += p.w;
    }
    *(float4*)(C + off) = s;
}

// ---------------- compress as gather-A GEMM, split-K x8 ----------------
__global__ __launch_bounds__(256) void compress_gemm_kernel(
    const float* __restrict__ kin, const float* __restrict__ vin,
    const float* __restrict__ kpe, const float* __restrict__ vpe,
    const float* __restrict__ Wkc, const float* __restrict__ Wvc,
    float* __restrict__ part)
{
    const float* in; const float* pe; const float* Wc;
    if (blockIdx.y == 0) { in = kin; pe = kpe; Wc = Wkc; }
    else                 { in = vin; pe = vpe; Wc = Wvc; }
    float* out = part + ((size_t)(blockIdx.z * 2 + blockIdx.y)) * CM * 64;
    int k0 = blockIdx.z * 128;

    __shared__ __align__(16) float As[2][16][68];
    __shared__ __align__(16) float Bs[2][16][64];
    int tid = threadIdx.x;
    int tx = tid & 15, ty = tid >> 4;
    int row0 = blockIdx.x * 64;

    int am  = tid >> 2;
    int akq = tid & 3;
    int row = row0 + am;
    bool avalid = row < CM;
    int rr = avalid ? row : CM - 1;
    int bh = rr / NCC, j = rr - bh * NCC;
    int b = bh >> 3, hh = bh & 7;
    const float* kb = in + (size_t)b * NTOK * DIMM + hh * DHH;
    int j4 = j * 4;

    auto fetchA = [&](int e) -> float4 {
        float4 p = *(const float4*)(pe + e);
        int jj = e >> 6, d = e & 63;
        int tok = j4 + jj;
        if (tok < NTOK) {
            float4 kv = *(const float4*)(kb + (size_t)tok * DIMM + d);
            p.x += kv.x; p.y += kv.y; p.z += kv.z; p.w += kv.w;
        }
        return p;
    };

    int bkk = tid >> 4;
    int bnq = tid & 15;
    const float* Wptr = Wc + (size_t)(k0 + bkk) * 64 + bnq * 4;

    float4 a4 = avalid ? fetchA(k0 + akq * 4) : make_float4(0.f, 0.f, 0.f, 0.f);
    float4 b4 = *(const float4*)(Wptr);
    As[0][akq * 4 + 0][am] = a4.x;
    As[0][akq * 4 + 1][am] = a4.y;
    As[0][akq * 4 + 2][am] = a4.z;
    As[0][akq * 4 + 3][am] = a4.w;
    *(float4*)&Bs[0][bkk][bnq * 4] = b4;
    __syncthreads();

    float acc[4][4];
    #pragma unroll
    for (int i = 0; i < 4; i++)
        #pragma unroll
        for (int jq = 0; jq < 4; jq++) acc[i][jq] = 0.f;

    const int steps = 8;
    for (int ks = 0; ks < steps; ks++) {
        int cur = ks & 1;
        bool hn = (ks + 1 < steps);
        if (hn) {
            int e = k0 + (ks + 1) * 16 + akq * 4;
            a4 = avalid ? fetchA(e) : make_float4(0.f, 0.f, 0.f, 0.f);
            b4 = *(const float4*)(Wptr + (size_t)(ks + 1) * 16 * 64);
        }
        #pragma unroll
        for (int kk = 0; kk < 16; kk++) {
            float4 av = *(const float4*)&As[cur][kk][ty * 4];
            float4 bv = *(const float4*)&Bs[cur][kk][tx * 4];
            acc[0][0] += av.x * bv.x; acc[0][1] += av.x * bv.y; acc[0][2] += av.x * bv.z; acc[0][3] += av.x * bv.w;
            acc[1][0] += av.y * bv.x; acc[1][1] += av.y * bv.y; acc[1][2] += av.y * bv.z; acc[1][3] += av.y * bv.w;
            acc[2][0] += av.z * bv.x; acc[2][1] += av.z * bv.y; acc[2][2] += av.z * bv.z; acc[2][3] += av.z * bv.w;
            acc[3][0] += av.w * bv.x; acc[3][1] += av.w * bv.y; acc[3][2] += av.w * bv.z; acc[3][3] += av.w * bv.w;
        }
        if (hn) {
            int nxt = cur ^ 1;
            As[nxt][akq * 4 + 0][am] = a4.x;
            As[nxt][akq * 4 + 1][am] = a4.y;
            As[nxt][akq * 4 + 2][am] = a4.z;
            As[nxt][akq * 4 + 3][am] = a4.w;
            *(float4*)&Bs[nxt][bkk][bnq * 4] = b4;
            __syncthreads();
        }
    }
    #pragma unroll
    for (int i = 0; i < 4; i++) {
        int r = row0 + ty * 4 + i;
        if (r >= CM) continue;
        int c = tx * 4;
        *(float4*)(out + (size_t)r * 64 + c) =
            make_float4(acc[i][0], acc[i][1], acc[i][2], acc[i][3]);
    }
}

// ---------------- compressed attention + top-k (12 queries/block) ----------------
__global__ __launch_bounds__(256) void cattn_kernel(
    const float* __restrict__ q, const float* __restrict__ ck,
    const float* __restrict__ cv, float* __restrict__ outc,
    int* __restrict__ selb)
{
    __shared__ float cbuf[NCC * 65];
    __shared__ float qs[QCA * 64];
    __shared__ float sc[QCA][NCC];
    int blk = blockIdx.x;
    int qb = blk % NQBA, bh = blk / NQBA;
    int h = bh % HH, b = bh / HH;
    int i0 = qb * QCA;
    int tid = threadIdx.x;
    for (int idx = tid; idx < QCA * 64; idx += 256) {
        int u = idx >> 6, d2 = idx & 63, i = i0 + u;
        qs[idx] = (i < NTOK) ? q[((size_t)(b * NTOK + i)) * DIMM + h * DHH + d2] : 0.f;
    }
    const float* ckb = ck + (size_t)bh * NCC * DHH;
    for (int idx = tid; idx < NCC * 64; idx += 256) {
        int j = idx >> 6, d2 = idx & 63;
        cbuf[j * 65 + d2] = ckb[idx];
    }
    __syncthreads();
    for (int p = tid; p < QCA * NCC; p += 256) {
        int u = p / NCC, j = p % NCC;
        const float* cr = &cbuf[j * 65];
        const float* qr = &qs[u * 64];
        float a = 0.f;
        #pragma unroll
        for (int d2 = 0; d2 < 64; d2++) a += qr[d2] * cr[d2];
        sc[u][j] = a * 0.125f;
    }
    __syncthreads();
    int w = tid >> 5, ln = tid & 31;
    for (int u = w; u < QCA; u += 8) {
        float m = -1e30f;
        for (int j = ln; j < NCC; j += 32) m = fmaxf(m, sc[u][j]);
        #pragma unroll
        for (int o = 16; o; o >>= 1) m = fmaxf(m, __shfl_xor_sync(0xffffffffu, m, o));
        float s = 0.f;
        for (int j = ln; j < NCC; j += 32) { float e = expf(sc[u][j] - m); sc[u][j] = e; s += e; }
        #pragma unroll
        for (int o = 16; o; o >>= 1) s += __shfl_xor_sync(0xffffffffu, s, o);
        float inv = 1.f / s;
        for (int j = ln; j < NCC; j += 32) sc[u][j] *= inv;
    }
    __syncthreads();
    if (tid < QCA) {
        int i = i0 + tid;
        if (i < NTOK) {
            float imp[NSB];
            #pragma unroll
            for (int t = 0; t < NSB; t++) imp[t] = 0.f;
            for (int j = 0; j < NCC; j++) {
                int c = (j + 2) >> 4; if (c > NSB - 1) c = NSB - 1;
                imp[c] += sc[tid][j];
            }
            size_t gi = (size_t)bh * NTOK + i;
            #pragma unroll
            for (int t = 0; t < KSEL; t++) {
                float best = -1e30f; int bi = 0;
                #pragma unroll
                for (int sbv = 0; sbv < NSB; sbv++)
                    if (imp[sbv] > best) { best = imp[sbv]; bi = sbv; }
                selb[gi * KSEL + t] = bi;
                imp[bi] = -2e30f;
            }
        }
    }
    __syncthreads();
    const float* cvb = cv + (size_t)bh * NCC * DHH;
    for (int idx = tid; idx < NCC * 64; idx += 256) {
        int j = idx >> 6, d2 = idx & 63;
        cbuf[j * 65 + d2] = cvb[idx];
    }
    __syncthreads();
    for (int p = tid; p < QCA * 64; p += 256) {
        int u = p >> 6, d2 = p & 63;
        int i = i0 + u;
        if (i >= NTOK) continue;
        float a = 0.f;
        for (int j = 0; j < NCC; j++) a += sc[u][j] * cbuf[j * 65 + d2];
        outc[((size_t)(bh * NTOK + i)) * 64 + d2] = a;
    }
}

// ==== tiled: selected-block attn + sliding window + gate combine (16 q/block) ====
__global__ __launch_bounds__(256) void swc_tile_kernel(
    const float* __restrict__ q, const float* __restrict__ k,
    const float* __restrict__ v, const float* __restrict__ outc,
    const float* __restrict__ gate, const int* __restrict__ selb,
    float* __restrict__ attn)
{
    __shared__ float qs[QT * 64];
    __shared__ float kvb[64 * 65];
    __shared__ float ss[QT][256];
    __shared__ float pw[QT][33];
    __shared__ int   sb[QT][4];
    __shared__ unsigned smask;

    int bx = blockIdx.x;
    int qt = bx % NQT;
    int bh = bx / NQT;
    int hd = bh % HH, b = bh / HH;
    int i0 = qt * QT;
    int tid = threadIdx.x;
    int lane = tid & 31, w = tid >> 5;

    for (int idx = tid; idx < QT * 64; idx += 256) {
        int u = idx >> 6, d = idx & 63;
        int i = i0 + u;
        qs[idx] = (i < NTOK) ? q[((size_t)(b * NTOK + i)) * DIMM + hd * DHH + d] : 0.f;
    }
    if (tid == 0) smask = 0;
    if (tid < QT * 4) {
        int u = tid >> 2, c = tid & 3;
        int i = i0 + u;
        sb[u][c] = (i < NTOK) ? selb[((size_t)(bh * NTOK + i)) * KSEL + c] : -1;
    }
    __syncthreads();
    if (tid < QT * 4) {
        int s = sb[tid >> 2][tid & 3];
        if (s >= 0) atomicOr(&smask, 1u << s);
    }
    __syncthreads();
    unsigned mask = smask;

    const float* kbase = k + (size_t)b * NTOK * DIMM + hd * DHH;
    const float* vbase = v + (size_t)b * NTOK * DIMM + hd * DHH;

    for (int sblk = 0; sblk < NSB; sblk++) {
        if (!((mask >> sblk) & 1u)) continue;
        for (int idx = tid; idx < 4096; idx += 256) {
            int t = idx >> 6, d = idx & 63;
            int tok = sblk * 64 + t; int tk = tok < NTOK ? tok : NTOK - 1;
            kvb[t * 65 + d] = kbase[(size_t)tk * DIMM + d];
        }
        __syncthreads();
        #pragma unroll
        for (int uu = 0; uu < 2; uu++) {
            int u = w * 2 + uu;
            #pragma unroll
            for (int c = 0; c < 4; c++) {
                if (sb[u][c] != sblk) continue;
                const float* qr = &qs[u * 64];
                #pragma unroll
                for (int tt = 0; tt < 2; tt++) {
                    int t = lane + tt * 32;
                    const float* kr = &kvb[t * 65];
                    float a = 0.f;
                    #pragma unroll
                    for (int d = 0; d < 64; d++) a += qr[d] * kr[d];
                    int tok = sblk * 64 + t;
                    ss[u][c * 64 + t] = (tok < NTOK) ? a * 0.125f : -1e30f;
                }
            }
        }
        __syncthreads();
    }

    #pragma unroll
    for (int uu = 0; uu < 2; uu++) {
        int u = w * 2 + uu;
        if (i0 + u < NTOK) {
            float m = -1e30f;
            #pragma unroll
            for (int j = 0; j < 8; j++) m = fmaxf(m, ss[u][lane + j * 32]);
            #pragma unroll
            for (int o = 16; o; o >>= 1) m = fmaxf(m, __shfl_xor_sync(0xffffffffu, m, o));
            float s = 0.f;
            #pragma unroll
            for (int j = 0; j < 8; j++) {
                float e = expf(ss[u][lane + j * 32] - m);
                ss[u][lane + j * 32] = e; s += e;
            }
            #pragma unroll
            for (int o = 16; o; o >>= 1) s += __shfl_xor_sync(0xffffffffu, s, o);
            float inv = 1.f / s;
            #pragma unroll
            for (int j = 0; j < 8; j++) ss[u][lane + j * 32] *= inv;
        }
    }
    __syncthreads();

    float accs[2][2] = {{0.f, 0.f}, {0.f, 0.f}};
    for (int sblk = 0; sblk < NSB; sblk++) {
        if (!((mask >> sblk) & 1u)) continue;
        for (int idx = tid; idx < 4096; idx += 256) {
            int t = idx >> 6, d = idx & 63;
            int tok = sblk * 64 + t; int tk = tok < NTOK ? tok : NTOK - 1;
            kvb[t * 65 + d] = vbase[(size_t)tk * DIMM + d];
        }
        __syncthreads();
        #pragma unroll
        for (int uu = 0; uu < 2; uu++) {
            int u = w * 2 + uu;
            #pragma unroll
            for (int c = 0; c < 4; c++) {
                if (sb[u][c] != sblk) continue;
                const float* pr = &ss[u][c * 64];
                for (int t = 0; t < 64; t++) {
                    float p = pr[t];
                    accs[uu][0] += p * kvb[t * 65 + lane];
                    accs[uu][1] += p * kvb[t * 65 + lane + 32];
                }
            }
        }
        __syncthreads();
    }

    const int WROWS = QT + SWIN - 1;
    int base = i0 - SWIN / 2;
    for (int idx = tid; idx < WROWS * 64; idx += 256) {
        int r = idx >> 6, d = idx & 63;
        int pos = base + r; int p = pos < 0 ? 0 : (pos > NTOK - 1 ? NTOK - 1 : pos);
        kvb[r * 65 + d] = kbase[(size_t)p * DIMM + d];
    }
    __syncthreads();
    #pragma unroll
    for (int uu = 0; uu < 2; uu++) {
        int u = w * 2 + uu;
        int i = i0 + u;
        int pos = i + lane - SWIN / 2;
        bool valid = (i < NTOK) && pos >= 0 && pos < NTOK;
        int r = u + lane;
        const float* qr = &qs[u * 64];
        const float* kr = &kvb[r * 65];
        float a = 0.f;
        #pragma unroll
        for (int d = 0; d < 64; d++) a += qr[d] * kr[d];
        float s = valid ? a * 0.125f : -1e30f;
        float m = s;
        #pragma unroll
        for (int o = 16; o; o >>= 1) m = fmaxf(m, __shfl_xor_sync(0xffffffffu, m, o));
        float e = expf(s - m);
        float t = e;
        #pragma unroll
        for (int o = 16; o; o >>= 1) t += __shfl_xor_sync(0xffffffffu, t, o);
        pw[u][lane] = e / t;
    }
    __syncthreads();
    for (int idx = tid; idx < WROWS * 64; idx += 256) {
        int r = idx >> 6, d = idx & 63;
        int pos = base + r; int p = pos < 0 ? 0 : (pos > NTOK - 1 ? NTOK - 1 : pos);
        kvb[r * 65 + d] = vbase[(size_t)p * DIMM + d];
    }
    __syncthreads();
    float accw[2][2] = {{0.f, 0.f}, {0.f, 0.f}};
    #pragma unroll
    for (int uu = 0; uu < 2; uu++) {
        int u = w * 2 + uu;
        for (int ww = 0; ww < SWIN; ww++) {
            float p = pw[u][ww];
            accw[uu][0] += p * kvb[(u + ww) * 65 + lane];
            accw[uu][1] += p * kvb[(u + ww) * 65 + lane + 32];
        }
    }

    #pragma unroll
    for (int uu = 0; uu < 2; uu++) {
        int u = w * 2 + uu;
        int i = i0 + u;
        if (i >= NTOK) continue;
        int row = b * NTOK + i;
        const float* gp = gate + (size_t)row * 24 + hd * 3;
        float g0 = gp[0], g1 = gp[1], g2 = gp[2];
        size_t gi = (size_t)bh * NTOK + i;
        #pragma unroll
        for (int dd = 0; dd < 2; dd++) {
            int d = lane + dd * 32;
            attn[(size_t)row * DIMM + hd * DHH + d] =
                g0 * outc[gi * 64 + d] + g1 * accs[uu][dd] + g2 * accw[uu][dd];
        }
    }
}

// ---------------- classifier head ----------------
__global__ void head_kernel(const float* __restrict__ hb, const float* __restrict__ W,
                            const float* __restrict__ bias, float* __restrict__ out)
{
    int o = blockIdx.y * 256 + threadIdx.x;
    int b = blockIdx.x;
    if (o >= NCLS) return;
    const float* hr = hb + b * DIMM;
    float acc = bias[o];
    #pragma unroll 8
    for (int d = 0; d < DIMM; d++) acc += hr[d] * W[(size_t)d * NCLS + o];
    out[(size_t)b * NCLS + o] = acc;
}

// ---------------- launch ----------------
extern "C" void kernel_launch(void* const* d_in, const int* in_sizes, int n_in,
                              void* d_out, int out_size) {
    const float* img     = (const float*)d_in[0];
    const float* patch_w = (const float*)d_in[1];
    const float* patch_b = (const float*)d_in[2];
    const float* pos_emb = (const float*)d_in[3];
    const float* cls_tok = (const float*)d_in[4];
    const float* ln1_g   = (const float*)d_in[5];
    const float* ln1_b   = (const float*)d_in[6];
    const float* Wq      = (const float*)d_in[7];
    const float* Wk      = (const float*)d_in[8];
    const float* Wv      = (const float*)d_in[9];
    const float* Wg      = (const float*)d_in[10];
    const float* Wo      = (const float*)d_in[11];
    const float* kpe     = (const float*)d_in[12];
    const float* vpe     = (const float*)d_in[13];
    const float* Wkc     = (const float*)d_in[14];
    const float* Wvc     = (const float*)d_in[15];
    const float* ln2_g   = (const float*)d_in[16];
    const float* ln2_b   = (const float*)d_in[17];
    const float* ff_w1   = (const float*)d_in[18];
    const float* ff_b1   = (const float*)d_in[19];
    const float* ff_w2   = (const float*)d_in[20];
    const float* ff_b2   = (const float*)d_in[21];
    const float* hln_g   = (const float*)d_in[22];
    const float* hln_b   = (const float*)d_in[23];
    const float* head_w  = (const float*)d_in[24];
    const float* head_b  = (const float*)d_in[25];

    float *x, *h, *q, *k, *v, *gate, *ckcv, *outc, *attn, *mlp, *hb, *prt;
    int* selb;
    cudaGetSymbolAddress((void**)&x, g_x);
    cudaGetSymbolAddress((void**)&h, g_h);
    cudaGetSymbolAddress((void**)&q, g_q);
    cudaGetSymbolAddress((void**)&k, g_k);
    cudaGetSymbolAddress((void**)&v, g_v);
    cudaGetSymbolAddress((void**)&gate, g_gate);
    cudaGetSymbolAddress((void**)&ckcv, g_ckcv);
    cudaGetSymbolAddress((void**)&outc, g_outc);
    cudaGetSymbolAddress((void**)&selb, g_selb);
    cudaGetSymbolAddress((void**)&attn, g_attn);
    cudaGetSymbolAddress((void**)&mlp, g_mlp);
    cudaGetSymbolAddress((void**)&hb, g_hb);
    cudaGetSymbolAddress((void**)&prt, g_part);

    const int CCN4 = (2 * CM * 64) / 4;
    const int CCRG = (CCN4 + 255) / 256;
    float* ck = ckcv;
    float* cv = ckcv + (size_t)CM * 64;

    patch_embed_kernel<<<BB * NTOK, 256>>>(img, patch_w, patch_b, pos_emb, cls_tok, x);
    ln_kernel<<<BN, 256>>>(x, DIMM, h, ln1_g, ln1_b);

    for (int l = 0; l < 2; l++) {
        const float* Wql = Wq + (size_t)l * DIMM * DIMM;
        const float* Wkl = Wk + (size_t)l * DIMM * DIMM;
        const float* Wvl = Wv + (size_t)l * DIMM * DIMM;
        const float* Wgl = Wg + (size_t)l * DIMM * 24;
        const float* Wol = Wo + (size_t)l * DIMM * DIMM;
        const float* kpel = kpe + (size_t)l * 16 * DHH;
        const float* vpel = vpe + (size_t)l * 16 * DHH;
        const float* Wkcl = Wkc + (size_t)l * 1024 * DHH;
        const float* Wvcl = Wvc + (size_t)l * 1024 * DHH;

        qkvgW_kernel<<<dim3(13, 19), 256>>>(h, Wql, Wkl, Wvl, Wgl, q, k, v, gate);

        compress_gemm_kernel<<<dim3((CM + 63) / 64, 2, 8), 256>>>(
            k, v, kpel, vpel, Wkcl, Wvcl, prt);
        reduce4_kernel<<<CCRG, 256>>>(prt, ckcv, CCN4, 8);

        cattn_kernel<<<BB * HH * NQBA, 256>>>(q, ck, cv, outc, selb);
        swc_tile_kernel<<<BB * HH * NQT, 256>>>(q, k, v, outc, gate, selb, attn);

        gemmW_split_kernel<<<dim3(4, 19, 4), 256>>>(attn, Wol, prt, BN, DIMM, DIMM);
        reduce_ln_kernel<<<BN, 128>>>(prt, (const float*)0, x, x,
                                      ln2_g + l * DIMM, ln2_b + l * DIMM, h, 4);

        // ff1: 128x128 8x8 core (grid 16x10 = 160), bias+GELU fused
        gemm128_kernel<<<dim3(16, 10), 256>>>(h, ff_w1 + (size_t)l * DIMM * MLPD,
                                              ff_b1 + (size_t)l * MLPD, mlp,
                                              BN, MLPD, DIMM);

        gemmW_split_kernel<<<dim3(4, 19, 4), 256>>>(mlp, ff_w2 + (size_t)l * MLPD * DIMM,
                                                    prt, BN, DIMM, MLPD);
        if (l == 0) {
            reduce_ln_kernel<<<BN, 128>>>(prt, ff_b2, x, x,
                                          ln1_g + DIMM, ln1_b + DIMM, h, 4);
        } else {
            reduce_ln_kernel<<<BN, 128>>>(prt, ff_b2 + (size_t)l * DIMM, x, x,
                                          (const float*)0, (const float*)0, h, 4);
        }
    }

    ln_kernel<<<BB, 256>>>(x, (long)NTOK * DIMM, hb, hln_g, hln_b);
    head_kernel<<<dim3(BB, (NCLS + 255) / 256), 256>>>(hb, head_w, head_b, (float*)d_out);
}

// round 15
// speedup vs baseline: 1.1006x; 1.1006x over previous
#include <cuda_runtime.h>
#include <math.h>

// ---------------- problem constants ----------------
#define BB   2
#define NTOK 577
#define DIMM 512
#define HH   8
#define DHH  64
#define NCC  145
#define NSB  10
#define KSEL 4
#define SWIN 32
#define MLPD 2048
#define NCLS 1000
#define BN   (BB*NTOK)    // 1154
#define QCA  12
#define NQBA 49
#define CM   (BB*HH*NCC)  // 2320
#define QT   16
#define NQT  37
#define PARTSZ (16*CM*64)

#define ACT_NONE 0
#define ACT_GELU 1
#define ACT_SIG  2

// ---------------- device scratch ----------------
__device__ float g_x   [BN*DIMM];
__device__ float g_h   [BN*DIMM];
__device__ float g_q   [BN*DIMM];
__device__ float g_k   [BN*DIMM];
__device__ float g_v   [BN*DIMM];
__device__ float g_gate[BN*24];
__device__ float g_ckcv[2*CM*DHH];
__device__ float g_outc[BB*HH*NTOK*DHH];
__device__ int   g_selb[BB*HH*NTOK*KSEL];
__device__ float g_attn[BN*DIMM];
__device__ float g_mlp [BN*MLPD];
__device__ float g_part[PARTSZ];

// ---------------- helpers ----------------
__device__ __forceinline__ float gelu_tanh(float x) {
    float x3 = x * x * x;
    return 0.5f * x * (1.0f + tanhf(0.7978845608028654f * (x + 0.044715f * x3)));
}

__device__ __forceinline__ float blk_sum256(float v, float* sred) {
    #pragma unroll
    for (int o = 16; o; o >>= 1) v += __shfl_xor_sync(0xffffffffu, v, o);
    __syncthreads();
    if ((threadIdx.x & 31) == 0) sred[threadIdx.x >> 5] = v;
    __syncthreads();
    float r = sred[0];
    #pragma unroll
    for (int w = 1; w < 8; w++) r += sred[w];
    return r;
}
__device__ __forceinline__ float blk_sum128(float v, float* sred) {
    #pragma unroll
    for (int o = 16; o; o >>= 1) v += __shfl_xor_sync(0xffffffffu, v, o);
    __syncthreads();
    if ((threadIdx.x & 31) == 0) sred[threadIdx.x >> 5] = v;
    __syncthreads();
    return sred[0] + sred[1] + sred[2] + sred[3];
}

// ---------------- patch embed + cls + pos + fused LN1(layer0) ----------------
__global__ __launch_bounds__(256) void patch_embed_ln_kernel(
    const float* __restrict__ img, const float* __restrict__ pw,
    const float* __restrict__ pb, const float* __restrict__ pos,
    const float* __restrict__ cls,
    const float* __restrict__ g, const float* __restrict__ bb,
    float* __restrict__ x, float* __restrict__ h)
{
    __shared__ float sred[8];
    int t = blockIdx.x % NTOK;
    int b = blockIdx.x / NTOK;
    int tid = threadIdx.x;
    float val[2];
    #pragma unroll
    for (int half = 0; half < 2; half++) {
        int d = tid + half * 256;
        float v;
        if (t == 0) {
            v = cls[d];
        } else {
            int p = t - 1;
            int ii = p / 24, jj = p % 24;
            v = pb[d];
            #pragma unroll
            for (int c = 0; c < 3; c++)
                v += img[((b * 3 + c) * 24 + ii) * 24 + jj] * pw[c * DIMM + d];
        }
        val[half] = v + pos[(size_t)t * DIMM + d];
    }
    size_t off = (size_t)(b * NTOK + t) * DIMM;
    x[off + tid]       = val[0];
    x[off + tid + 256] = val[1];
    float mean = blk_sum256(val[0] + val[1], sred) * (1.0f / 512.0f);
    float d0 = val[0] - mean, d1 = val[1] - mean;
    __syncthreads();
    float var = blk_sum256(d0 * d0 + d1 * d1, sred) * (1.0f / 512.0f);
    float inv = rsqrtf(var + 1e-5f);
    h[off + tid]       = d0 * inv * g[tid] + bb[tid];
    h[off + tid + 256] = d1 * inv * g[tid + 256] + bb[tid + 256];
}

// ---------------- SGEMM core A: 64x64 tile, 4x4/thread ----------------
__device__ __forceinline__ void gemm_core(
    const float* __restrict__ A, const float* __restrict__ W,
    const float* __restrict__ bias, const float* __restrict__ res,
    float* __restrict__ C, float* __restrict__ part,
    int M, int Nn, int K, int act, int row0, int col0, int k0, int kLen)
{
    __shared__ __align__(16) float As[2][16][68];
    __shared__ __align__(16) float Bs[2][16][64];
    int tid = threadIdx.x;
    int tx = tid & 15, ty = tid >> 4;

    int am  = tid >> 2;
    int akq = tid & 3;
    int arow = row0 + am;
    const float* Aptr = (arow < M) ? (A + (size_t)arow * K + k0 + akq * 4) : (const float*)0;
    int bkk = tid >> 4;
    int bnq = tid & 15;
    int bcol = col0 + bnq * 4;
    const float* Wptr = W + (size_t)(k0 + bkk) * Nn + bcol;
    bool bfull = (bcol + 3 < Nn);
    bool bany  = (bcol < Nn);

    float4 a4, b4;
    if (Aptr) a4 = *(const float4*)(Aptr);
    else      a4 = make_float4(0.f, 0.f, 0.f, 0.f);
    if (bfull) b4 = *(const float4*)(Wptr);
    else {
        b4 = make_float4(0.f, 0.f, 0.f, 0.f);
        if (bany) {
            b4.x = Wptr[0];
            if (bcol + 1 < Nn) b4.y = Wptr[1];
            if (bcol + 2 < Nn) b4.z = Wptr[2];
        }
    }
    As[0][akq * 4 + 0][am] = a4.x;
    As[0][akq * 4 + 1][am] = a4.y;
    As[0][akq * 4 + 2][am] = a4.z;
    As[0][akq * 4 + 3][am] = a4.w;
    *(float4*)&Bs[0][bkk][bnq * 4] = b4;
    __syncthreads();

    float acc[4][4];
    #pragma unroll
    for (int i = 0; i < 4; i++)
        #pragma unroll
        for (int j = 0; j < 4; j++) acc[i][j] = 0.f;

    int steps = kLen >> 4;
    for (int ks = 0; ks < steps; ks++) {
        int cur = ks & 1;
        bool hn = (ks + 1 < steps);
        if (hn) {
            int kk0 = (ks + 1) * 16;
            if (Aptr) a4 = *(const float4*)(Aptr + kk0);
            else      a4 = make_float4(0.f, 0.f, 0.f, 0.f);
            if (bfull) b4 = *(const float4*)(Wptr + (size_t)kk0 * Nn);
            else {
                b4 = make_float4(0.f, 0.f, 0.f, 0.f);
                if (bany) {
                    const float* p = Wptr + (size_t)kk0 * Nn;
                    b4.x = p[0];
                    if (bcol + 1 < Nn) b4.y = p[1];
                    if (bcol + 2 < Nn) b4.z = p[2];
                }
            }
        }
        #pragma unroll
        for (int kk = 0; kk < 16; kk++) {
            float4 av = *(const float4*)&As[cur][kk][ty * 4];
            float4 bv = *(const float4*)&Bs[cur][kk][tx * 4];
            acc[0][0] += av.x * bv.x; acc[0][1] += av.x * bv.y; acc[0][2] += av.x * bv.z; acc[0][3] += av.x * bv.w;
            acc[1][0] += av.y * bv.x; acc[1][1] += av.y * bv.y; acc[1][2] += av.y * bv.z; acc[1][3] += av.y * bv.w;
            acc[2][0] += av.z * bv.x; acc[2][1] += av.z * bv.y; acc[2][2] += av.z * bv.z; acc[2][3] += av.z * bv.w;
            acc[3][0] += av.w * bv.x; acc[3][1] += av.w * bv.y; acc[3][2] += av.w * bv.z; acc[3][3] += av.w * bv.w;
        }
        if (hn) {
            int nxt = cur ^ 1;
            As[nxt][akq * 4 + 0][am] = a4.x;
            As[nxt][akq * 4 + 1][am] = a4.y;
            As[nxt][akq * 4 + 2][am] = a4.z;
            As[nxt][akq * 4 + 3][am] = a4.w;
            *(float4*)&Bs[nxt][bkk][bnq * 4] = b4;
            __syncthreads();
        }
    }
    #pragma unroll
    for (int i = 0; i < 4; i++) {
        int r = row0 + ty * 4 + i;
        if (r >= M) continue;
        #pragma unroll
        for (int j = 0; j < 4; j++) {
            int c = col0 + tx * 4 + j;
            if (c >= Nn) continue;
            float v = acc[i][j];
            size_t off = (size_t)r * Nn + c;
            if (part) {
                part[off] = v;
            } else {
                if (bias) v += bias[c];
                if (act == ACT_GELU) v = gelu_tanh(v);
                else if (act == ACT_SIG) v = 1.0f / (1.0f + expf(-v));
                if (res) v += res[off];
                C[off] = v;
            }
        }
    }
}

// ---------------- SGEMM core B: 64x128 tile, 4x8/thread ----------------
__device__ __forceinline__ void gemmW_core(
    const float* __restrict__ A, const float* __restrict__ W,
    const float* __restrict__ bias, const float* __restrict__ res,
    float* __restrict__ C, float* __restrict__ part,
    int M, int Nn, int K, int act, int row0, int col0, int k0, int kLen)
{
    __shared__ __align__(16) float As[2][16][68];
    __shared__ __align__(16) float Bs[2][16][128];
    int tid = threadIdx.x;
    int tx = tid & 15, ty = tid >> 4;

    int am  = tid >> 2;
    int akq = tid & 3;
    int arow = row0 + am;
    const float* Aptr = (arow < M) ? (A + (size_t)arow * K + k0 + akq * 4) : (const float*)0;
    int bkk = tid >> 4;
    int bnq = tid & 15;
    const float* Wptr = W + (size_t)(k0 + bkk) * Nn + col0 + bnq * 4;

    float4 a4, b4a, b4b;
    if (Aptr) a4 = *(const float4*)(Aptr);
    else      a4 = make_float4(0.f, 0.f, 0.f, 0.f);
    b4a = *(const float4*)(Wptr);
    b4b = *(const float4*)(Wptr + 64);
    As[0][akq * 4 + 0][am] = a4.x;
    As[0][akq * 4 + 1][am] = a4.y;
    As[0][akq * 4 + 2][am] = a4.z;
    As[0][akq * 4 + 3][am] = a4.w;
    *(float4*)&Bs[0][bkk][bnq * 4]      = b4a;
    *(float4*)&Bs[0][bkk][64 + bnq * 4] = b4b;
    __syncthreads();

    float acc[4][8];
    #pragma unroll
    for (int i = 0; i < 4; i++)
        #pragma unroll
        for (int j = 0; j < 8; j++) acc[i][j] = 0.f;

    int steps = kLen >> 4;
    for (int ks = 0; ks < steps; ks++) {
        int cur = ks & 1;
        bool hn = (ks + 1 < steps);
        if (hn) {
            int kk0 = (ks + 1) * 16;
            if (Aptr) a4 = *(const float4*)(Aptr + kk0);
            else      a4 = make_float4(0.f, 0.f, 0.f, 0.f);
            const float* p = Wptr + (size_t)kk0 * Nn;
            b4a = *(const float4*)(p);
            b4b = *(const float4*)(p + 64);
        }
        #pragma unroll
        for (int kk = 0; kk < 16; kk++) {
            float4 av = *(const float4*)&As[cur][kk][ty * 4];
            float4 bv0 = *(const float4*)&Bs[cur][kk][tx * 4];
            float4 bv1 = *(const float4*)&Bs[cur][kk][64 + tx * 4];
            float a0 = av.x, a1 = av.y, a2 = av.z, a3 = av.w;
            acc[0][0] += a0 * bv0.x; acc[0][1] += a0 * bv0.y; acc[0][2] += a0 * bv0.z; acc[0][3] += a0 * bv0.w;
            acc[0][4] += a0 * bv1.x; acc[0][5] += a0 * bv1.y; acc[0][6] += a0 * bv1.z; acc[0][7] += a0 * bv1.w;
            acc[1][0] += a1 * bv0.x; acc[1][1] += a1 * bv0.y; acc[1][2] += a1 * bv0.z; acc[1][3] += a1 * bv0.w;
            acc[1][4] += a1 * bv1.x; acc[1][5] += a1 * bv1.y; acc[1][6] += a1 * bv1.z; acc[1][7] += a1 * bv1.w;
            acc[2][0] += a2 * bv0.x; acc[2][1] += a2 * bv0.y; acc[2][2] += a2 * bv0.z; acc[2][3] += a2 * bv0.w;
            acc[2][4] += a2 * bv1.x; acc[2][5] += a2 * bv1.y; acc[2][6] += a2 * bv1.z; acc[2][7] += a2 * bv1.w;
            acc[3][0] += a3 * bv0.x; acc[3][1] += a3 * bv0.y; acc[3][2] += a3 * bv0.z; acc[3][3] += a3 * bv0.w;
            acc[3][4] += a3 * bv1.x; acc[3][5] += a3 * bv1.y; acc[3][6] += a3 * bv1.z; acc[3][7] += a3 * bv1.w;
        }
        if (hn) {
            int nxt = cur ^ 1;
            As[nxt][akq * 4 + 0][am] = a4.x;
            As[nxt][akq * 4 + 1][am] = a4.y;
            As[nxt][akq * 4 + 2][am] = a4.z;
            As[nxt][akq * 4 + 3][am] = a4.w;
            *(float4*)&Bs[nxt][bkk][bnq * 4]      = b4a;
            *(float4*)&Bs[nxt][bkk][64 + bnq * 4] = b4b;
            __syncthreads();
        }
    }
    #pragma unroll
    for (int i = 0; i < 4; i++) {
        int r = row0 + ty * 4 + i;
        if (r >= M) continue;
        #pragma unroll
        for (int half = 0; half < 2; half++) {
            int c = col0 + half * 64 + tx * 4;
            size_t off = (size_t)r * Nn + c;
            float4 v;
            v.x = acc[i][half * 4 + 0]; v.y = acc[i][half * 4 + 1];
            v.z = acc[i][half * 4 + 2]; v.w = acc[i][half * 4 + 3];
            if (part) {
                *(float4*)(part + off) = v;
            } else {
                if (bias) {
                    v.x += bias[c]; v.y += bias[c + 1];
                    v.z += bias[c + 2]; v.w += bias[c + 3];
                }
                if (act == ACT_GELU) {
                    v.x = gelu_tanh(v.x); v.y = gelu_tanh(v.y);
                    v.z = gelu_tanh(v.z); v.w = gelu_tanh(v.w);
                }
                if (res) {
                    float4 r4 = *(const float4*)(res + off);
                    v.x += r4.x; v.y += r4.y; v.z += r4.z; v.w += r4.w;
                }
                *(float4*)(C + off) = v;
            }
        }
    }
}

__global__ __launch_bounds__(256) void gemmW_kernel(
    const float* __restrict__ A, const float* __restrict__ W,
    const float* __restrict__ bias, const float* __restrict__ res,
    float* __restrict__ C, int M, int Nn, int K, int act)
{
    gemmW_core(A, W, bias, res, C, (float*)0, M, Nn, K, act,
               blockIdx.y * 64, blockIdx.x * 128, 0, K);
}

__global__ __launch_bounds__(256) void gemmW_split_kernel(
    const float* __restrict__ A, const float* __restrict__ W,
    float* __restrict__ part, int M, int Nn, int K)
{
    int chunk = K / gridDim.z;
    float* p = part + (size_t)blockIdx.z * M * Nn;
    gemmW_core(A, W, (const float*)0, (const float*)0, (float*)0, p,
               M, Nn, K, ACT_NONE,
               blockIdx.y * 64, blockIdx.x * 128, blockIdx.z * chunk, chunk);
}

// fused QKV (64x128 core) + gate (64x64 core)
__global__ __launch_bounds__(256) void qkvgW_kernel(
    const float* __restrict__ h,
    const float* __restrict__ Wq, const float* __restrict__ Wk,
    const float* __restrict__ Wv, const float* __restrict__ Wg,
    float* __restrict__ q, float* __restrict__ k,
    float* __restrict__ v, float* __restrict__ gate)
{
    int bx = blockIdx.x;
    if (bx < 12) {
        int sel = bx >> 2;
        const float* W; float* C;
        if (sel == 0)      { W = Wq; C = q; }
        else if (sel == 1) { W = Wk; C = k; }
        else               { W = Wv; C = v; }
        gemmW_core(h, W, (const float*)0, (const float*)0, C, (float*)0,
                   BN, DIMM, DIMM, ACT_NONE, blockIdx.y * 64, (bx & 3) * 128, 0, DIMM);
    } else {
        gemm_core(h, Wg, (const float*)0, (const float*)0, gate, (float*)0,
                  BN, 24, DIMM, ACT_SIG, blockIdx.y * 64, 0, 0, DIMM);
    }
}

// ---------------- fused split-K reduce + residual + LayerNorm ----------------
__global__ __launch_bounds__(128) void reduce_ln_kernel(
    const float* __restrict__ part, const float* __restrict__ bias,
    const float* __restrict__ res, float* __restrict__ x,
    const float* __restrict__ gamma, const float* __restrict__ beta,
    float* __restrict__ h, int S)
{
    __shared__ float sred[4];
    int r = blockIdx.x;
    int t = threadIdx.x;
    int c = t * 4;
    size_t off = (size_t)r * DIMM + c;
    size_t stride = (size_t)BN * DIMM;
    float4 s = *(const float4*)(part + off);
    for (int i = 1; i < S; i++) {
        float4 p = *(const float4*)(part + (size_t)i * stride + off);
        s.x += p.x; s.y += p.y; s.z += p.z; s.w += p.w;
    }
    if (bias) {
        s.x += bias[c]; s.y += bias[c + 1]; s.z += bias[c + 2]; s.w += bias[c + 3];
    }
    if (res) {
        float4 r4 = *(const float4*)(res + off);
        s.x += r4.x; s.y += r4.y; s.z += r4.z; s.w += r4.w;
    }
    *(float4*)(x + off) = s;
    if (!gamma) return;
    float mean = blk_sum128(s.x + s.y + s.z + s.w, sred) * (1.0f / 512.0f);
    float d0 = s.x - mean, d1 = s.y - mean, d2 = s.z - mean, d3 = s.w - mean;
    __syncthreads();
    float var = blk_sum128(d0 * d0 + d1 * d1 + d2 * d2 + d3 * d3, sred) * (1.0f / 512.0f);
    float inv = rsqrtf(var + 1e-5f);
    float4 o;
    o.x = d0 * inv * gamma[c]     + beta[c];
    o.y = d1 * inv * gamma[c + 1] + beta[c + 1];
    o.z = d2 * inv * gamma[c + 2] + beta[c + 2];
    o.w = d3 * inv * gamma[c + 3] + beta[c + 3];
    *(float4*)(h + off) = o;
}

// generic split-K reduce (compress path)
__global__ __launch_bounds__(256) void reduce4_kernel(
    const float* __restrict__ part, float* __restrict__ C, int MN4, int S)
{
    int idx = blockIdx.x * 256 + threadIdx.x;
    if (idx >= MN4) return;
    size_t off = (size_t)idx * 4;
    size_t stride = (size_t)MN4 * 4;
    float4 s = *(const float4*)(part + off);
    for (int t = 1; t < S; t++) {
        float4 p = *(const float4*)(part + (size_t)t * stride + off);
        s.x += p.x; s.y += p.y; s.z += p.z; s.w += p.w;
    }
    *(float4*)(C + off) = s;
}

// ---------------- compress as gather-A GEMM, split-K x8 ----------------
__global__ __launch_bounds__(256) void compress_gemm_kernel(
    const float* __restrict__ kin, const float* __restrict__ vin,
    const float* __restrict__ kpe, const float* __restrict__ vpe,
    const float* __restrict__ Wkc, const float* __restrict__ Wvc,
    float* __restrict__ part)
{
    const float* in; const float* pe; const float* Wc;
    if (blockIdx.y == 0) { in = kin; pe = kpe; Wc = Wkc; }
    else                 { in = vin; pe = vpe; Wc = Wvc; }
    float* out = part + ((size_t)(blockIdx.z * 2 + blockIdx.y)) * CM * 64;
    int k0 = blockIdx.z * 128;

    __shared__ __align__(16) float As[2][16][68];
    __shared__ __align__(16) float Bs[2][16][64];
    int tid = threadIdx.x;
    int tx = tid & 15, ty = tid >> 4;
    int row0 = blockIdx.x * 64;

    int am  = tid >> 2;
    int akq = tid & 3;
    int row = row0 + am;
    bool avalid = row < CM;
    int rr = avalid ? row : CM - 1;
    int bh = rr / NCC, j = rr - bh * NCC;
    int b = bh >> 3, hh = bh & 7;
    const float* kb = in + (size_t)b * NTOK * DIMM + hh * DHH;
    int j4 = j * 4;

    auto fetchA = [&](int e) -> float4 {
        float4 p = *(const float4*)(pe + e);
        int jj = e >> 6, d = e & 63;
        int tok = j4 + jj;
        if (tok < NTOK) {
            float4 kv = *(const float4*)(kb + (size_t)tok * DIMM + d);
            p.x += kv.x; p.y += kv.y; p.z += kv.z; p.w += kv.w;
        }
        return p;
    };

    int bkk = tid >> 4;
    int bnq = tid & 15;
    const float* Wptr = Wc + (size_t)(k0 + bkk) * 64 + bnq * 4;

    float4 a4 = avalid ? fetchA(k0 + akq * 4) : make_float4(0.f, 0.f, 0.f, 0.f);
    float4 b4 = *(const float4*)(Wptr);
    As[0][akq * 4 + 0][am] = a4.x;
    As[0][akq * 4 + 1][am] = a4.y;
    As[0][akq * 4 + 2][am] = a4.z;
    As[0][akq * 4 + 3][am] = a4.w;
    *(float4*)&Bs[0][bkk][bnq * 4] = b4;
    __syncthreads();

    float acc[4][4];
    #pragma unroll
    for (int i = 0; i < 4; i++)
        #pragma unroll
        for (int jq = 0; jq < 4; jq++) acc[i][jq] = 0.f;

    const int steps = 8;
    for (int ks = 0; ks < steps; ks++) {
        int cur = ks & 1;
        bool hn = (ks + 1 < steps);
        if (hn) {
            int e = k0 + (ks + 1) * 16 + akq * 4;
            a4 = avalid ? fetchA(e) : make_float4(0.f, 0.f, 0.f, 0.f);
            b4 = *(const float4*)(Wptr + (size_t)(ks + 1) * 16 * 64);
        }
        #pragma unroll
        for (int kk = 0; kk < 16; kk++) {
            float4 av = *(const float4*)&As[cur][kk][ty * 4];
            float4 bv = *(const float4*)&Bs[cur][kk][tx * 4];
            acc[0][0] += av.x * bv.x; acc[0][1] += av.x * bv.y; acc[0][2] += av.x * bv.z; acc[0][3] += av.x * bv.w;
            acc[1][0] += av.y * bv.x; acc[1][1] += av.y * bv.y; acc[1][2] += av.y * bv.z; acc[1][3] += av.y * bv.w;
            acc[2][0] += av.z * bv.x; acc[2][1] += av.z * bv.y; acc[2][2] += av.z * bv.z; acc[2][3] += av.z * bv.w;
            acc[3][0] += av.w * bv.x; acc[3][1] += av.w * bv.y; acc[3][2] += av.w * bv.z; acc[3][3] += av.w * bv.w;
        }
        if (hn) {
            int nxt = cur ^ 1;
            As[nxt][akq * 4 + 0][am] = a4.x;
            As[nxt][akq * 4 + 1][am] = a4.y;
            As[nxt][akq * 4 + 2][am] = a4.z;
            As[nxt][akq * 4 + 3][am] = a4.w;
            *(float4*)&Bs[nxt][bkk][bnq * 4] = b4;
            __syncthreads();
        }
    }
    #pragma unroll
    for (int i = 0; i < 4; i++) {
        int r = row0 + ty * 4 + i;
        if (r >= CM) continue;
        int c = tx * 4;
        *(float4*)(out + (size_t)r * 64 + c) =
            make_float4(acc[i][0], acc[i][1], acc[i][2], acc[i][3]);
    }
}

// ---------------- compressed attention + top-k (12 queries/block) ----------------
__global__ __launch_bounds__(256) void cattn_kernel(
    const float* __restrict__ q, const float* __restrict__ ck,
    const float* __restrict__ cv, float* __restrict__ outc,
    int* __restrict__ selb)
{
    __shared__ float cbuf[NCC * 65];
    __shared__ float qs[QCA * 64];
    __shared__ float sc[QCA][NCC];
    int blk = blockIdx.x;
    int qb = blk % NQBA, bh = blk / NQBA;
    int h = bh % HH, b = bh / HH;
    int i0 = qb * QCA;
    int tid = threadIdx.x;
    for (int idx = tid; idx < QCA * 64; idx += 256) {
        int u = idx >> 6, d2 = idx & 63, i = i0 + u;
        qs[idx] = (i < NTOK) ? q[((size_t)(b * NTOK + i)) * DIMM + h * DHH + d2] : 0.f;
    }
    const float* ckb = ck + (size_t)bh * NCC * DHH;
    for (int idx = tid; idx < NCC * 64; idx += 256) {
        int j = idx >> 6, d2 = idx & 63;
        cbuf[j * 65 + d2] = ckb[idx];
    }
    __syncthreads();
    for (int p = tid; p < QCA * NCC; p += 256) {
        int u = p / NCC, j = p % NCC;
        const float* cr = &cbuf[j * 65];
        const float* qr = &qs[u * 64];
        float a = 0.f;
        #pragma unroll
        for (int d2 = 0; d2 < 64; d2++) a += qr[d2] * cr[d2];
        sc[u][j] = a * 0.125f;
    }
    __syncthreads();
    int w = tid >> 5, ln = tid & 31;
    for (int u = w; u < QCA; u += 8) {
        float m = -1e30f;
        for (int j = ln; j < NCC; j += 32) m = fmaxf(m, sc[u][j]);
        #pragma unroll
        for (int o = 16; o; o >>= 1) m = fmaxf(m, __shfl_xor_sync(0xffffffffu, m, o));
        float s = 0.f;
        for (int j = ln; j < NCC; j += 32) { float e = expf(sc[u][j] - m); sc[u][j] = e; s += e; }
        #pragma unroll
        for (int o = 16; o; o >>= 1) s += __shfl_xor_sync(0xffffffffu, s, o);
        float inv = 1.f / s;
        for (int j = ln; j < NCC; j += 32) sc[u][j] *= inv;
    }
    __syncthreads();
    if (tid < QCA) {
        int i = i0 + tid;
        if (i < NTOK) {
            float imp[NSB];
            #pragma unroll
            for (int t = 0; t < NSB; t++) imp[t] = 0.f;
            for (int j = 0; j < NCC; j++) {
                int c = (j + 2) >> 4; if (c > NSB - 1) c = NSB - 1;
                imp[c] += sc[tid][j];
            }
            size_t gi = (size_t)bh * NTOK + i;
            #pragma unroll
            for (int t = 0; t < KSEL; t++) {
                float best = -1e30f; int bi = 0;
                #pragma unroll
                for (int sbv = 0; sbv < NSB; sbv++)
                    if (imp[sbv] > best) { best = imp[sbv]; bi = sbv; }
                selb[gi * KSEL + t] = bi;
                imp[bi] = -2e30f;
            }
        }
    }
    __syncthreads();
    const float* cvb = cv + (size_t)bh * NCC * DHH;
    for (int idx = tid; idx < NCC * 64; idx += 256) {
        int j = idx >> 6, d2 = idx & 63;
        cbuf[j * 65 + d2] = cvb[idx];
    }
    __syncthreads();
    for (int p = tid; p < QCA * 64; p += 256) {
        int u = p >> 6, d2 = p & 63;
        int i = i0 + u;
        if (i >= NTOK) continue;
        float a = 0.f;
        for (int j = 0; j < NCC; j++) a += sc[u][j] * cbuf[j * 65 + d2];
        outc[((size_t)(bh * NTOK + i)) * 64 + d2] = a;
    }
}

// ==== tiled: selected-block attn + sliding window + gate combine (16 q/block) ====
__global__ __launch_bounds__(256) void swc_tile_kernel(
    const float* __restrict__ q, const float* __restrict__ k,
    const float* __restrict__ v, const float* __restrict__ outc,
    const float* __restrict__ gate, const int* __restrict__ selb,
    float* __restrict__ attn)
{
    __shared__ float qs[QT * 64];
    __shared__ float kvb[64 * 65];
    __shared__ float ss[QT][256];
    __shared__ float pw[QT][33];
    __shared__ int   sb[QT][4];
    __shared__ unsigned smask;

    int bx = blockIdx.x;
    int qt = bx % NQT;
    int bh = bx / NQT;
    int hd = bh % HH, b = bh / HH;
    int i0 = qt * QT;
    int tid = threadIdx.x;
    int lane = tid & 31, w = tid >> 5;

    for (int idx = tid; idx < QT * 64; idx += 256) {
        int u = idx >> 6, d = idx & 63;
        int i = i0 + u;
        qs[idx] = (i < NTOK) ? q[((size_t)(b * NTOK + i)) * DIMM + hd * DHH + d] : 0.f;
    }
    if (tid == 0) smask = 0;
    if (tid < QT * 4) {
        int u = tid >> 2, c = tid & 3;
        int i = i0 + u;
        sb[u][c] = (i < NTOK) ? selb[((size_t)(bh * NTOK + i)) * KSEL + c] : -1;
    }
    __syncthreads();
    if (tid < QT * 4) {
        int s = sb[tid >> 2][tid & 3];
        if (s >= 0) atomicOr(&smask, 1u << s);
    }
    __syncthreads();
    unsigned mask = smask;

    const float* kbase = k + (size_t)b * NTOK * DIMM + hd * DHH;
    const float* vbase = v + (size_t)b * NTOK * DIMM + hd * DHH;

    for (int sblk = 0; sblk < NSB; sblk++) {
        if (!((mask >> sblk) & 1u)) continue;
        for (int idx = tid; idx < 4096; idx += 256) {
            int t = idx >> 6, d = idx & 63;
            int tok = sblk * 64 + t; int tk = tok < NTOK ? tok : NTOK - 1;
            kvb[t * 65 + d] = kbase[(size_t)tk * DIMM + d];
        }
        __syncthreads();
        #pragma unroll
        for (int uu = 0; uu < 2; uu++) {
            int u = w * 2 + uu;
            #pragma unroll
            for (int c = 0; c < 4; c++) {
                if (sb[u][c] != sblk) continue;
                const float* qr = &qs[u * 64];
                #pragma unroll
                for (int tt = 0; tt < 2; tt++) {
                    int t = lane + tt * 32;
                    const float* kr = &kvb[t * 65];
                    float a = 0.f;
                    #pragma unroll
                    for (int d = 0; d < 64; d++) a += qr[d] * kr[d];
                    int tok = sblk * 64 + t;
                    ss[u][c * 64 + t] = (tok < NTOK) ? a * 0.125f : -1e30f;
                }
            }
        }
        __syncthreads();
    }

    #pragma unroll
    for (int uu = 0; uu < 2; uu++) {
        int u = w * 2 + uu;
        if (i0 + u < NTOK) {
            float m = -1e30f;
            #pragma unroll
            for (int j = 0; j < 8; j++) m = fmaxf(m, ss[u][lane + j * 32]);
            #pragma unroll
            for (int o = 16; o; o >>= 1) m = fmaxf(m, __shfl_xor_sync(0xffffffffu, m, o));
            float s = 0.f;
            #pragma unroll
            for (int j = 0; j < 8; j++) {
                float e = expf(ss[u][lane + j * 32] - m);
                ss[u][lane + j * 32] = e; s += e;
            }
            #pragma unroll
            for (int o = 16; o; o >>= 1) s += __shfl_xor_sync(0xffffffffu, s, o);
            float inv = 1.f / s;
            #pragma unroll
            for (int j = 0; j < 8; j++) ss[u][lane + j * 32] *= inv;
        }
    }
    __syncthreads();

    float accs[2][2] = {{0.f, 0.f}, {0.f, 0.f}};
    for (int sblk = 0; sblk < NSB; sblk++) {
        if (!((mask >> sblk) & 1u)) continue;
        for (int idx = tid; idx < 4096; idx += 256) {
            int t = idx >> 6, d = idx & 63;
            int tok = sblk * 64 + t; int tk = tok < NTOK ? tok : NTOK - 1;
            kvb[t * 65 + d] = vbase[(size_t)tk * DIMM + d];
        }
        __syncthreads();
        #pragma unroll
        for (int uu = 0; uu < 2; uu++) {
            int u = w * 2 + uu;
            #pragma unroll
            for (int c = 0; c < 4; c++) {
                if (sb[u][c] != sblk) continue;
                const float* pr = &ss[u][c * 64];
                for (int t = 0; t < 64; t++) {
                    float p = pr[t];
                    accs[uu][0] += p * kvb[t * 65 + lane];
                    accs[uu][1] += p * kvb[t * 65 + lane + 32];
                }
            }
        }
        __syncthreads();
    }

    const int WROWS = QT + SWIN - 1;
    int base = i0 - SWIN / 2;
    for (int idx = tid; idx < WROWS * 64; idx += 256) {
        int r = idx >> 6, d = idx & 63;
        int pos = base + r; int p = pos < 0 ? 0 : (pos > NTOK - 1 ? NTOK - 1 : pos);
        kvb[r * 65 + d] = kbase[(size_t)p * DIMM + d];
    }
    __syncthreads();
    #pragma unroll
    for (int uu = 0; uu < 2; uu++) {
        int u = w * 2 + uu;
        int i = i0 + u;
        int pos = i + lane - SWIN / 2;
        bool valid = (i < NTOK) && pos >= 0 && pos < NTOK;
        int r = u + lane;
        const float* qr = &qs[u * 64];
        const float* kr = &kvb[r * 65];
        float a = 0.f;
        #pragma unroll
        for (int d = 0; d < 64; d++) a += qr[d] * kr[d];
        float s = valid ? a * 0.125f : -1e30f;
        float m = s;
        #pragma unroll
        for (int o = 16; o; o >>= 1) m = fmaxf(m, __shfl_xor_sync(0xffffffffu, m, o));
        float e = expf(s - m);
        float t = e;
        #pragma unroll
        for (int o = 16; o; o >>= 1) t += __shfl_xor_sync(0xffffffffu, t, o);
        pw[u][lane] = e / t;
    }
    __syncthreads();
    for (int idx = tid; idx < WROWS * 64; idx += 256) {
        int r = idx >> 6, d = idx & 63;
        int pos = base + r; int p = pos < 0 ? 0 : (pos > NTOK - 1 ? NTOK - 1 : pos);
        kvb[r * 65 + d] = vbase[(size_t)p * DIMM + d];
    }
    __syncthreads();
    float accw[2][2] = {{0.f, 0.f}, {0.f, 0.f}};
    #pragma unroll
    for (int uu = 0; uu < 2; uu++) {
        int u = w * 2 + uu;
        for (int ww = 0; ww < SWIN; ww++) {
            float p = pw[u][ww];
            accw[uu][0] += p * kvb[(u + ww) * 65 + lane];
            accw[uu][1] += p * kvb[(u + ww) * 65 + lane + 32];
        }
    }

    #pragma unroll
    for (int uu = 0; uu < 2; uu++) {
        int u = w * 2 + uu;
        int i = i0 + u;
        if (i >= NTOK) continue;
        int row = b * NTOK + i;
        const float* gp = gate + (size_t)row * 24 + hd * 3;
        float g0 = gp[0], g1 = gp[1], g2 = gp[2];
        size_t gi = (size_t)bh * NTOK + i;
        #pragma unroll
        for (int dd = 0; dd < 2; dd++) {
            int d = lane + dd * 32;
            attn[(size_t)row * DIMM + hd * DHH + d] =
                g0 * outc[gi * 64 + d] + g1 * accs[uu][dd] + g2 * accw[uu][dd];
        }
    }
}

// ---------------- fused final LN + classifier head ----------------
// grid (BB, 4), 256 threads. Each block LNs its batch's token-0 row into smem,
// then computes 256 output classes.
__global__ __launch_bounds__(256) void head_ln_kernel(
    const float* __restrict__ x, const float* __restrict__ g,
    const float* __restrict__ bb, const float* __restrict__ W,
    const float* __restrict__ bias, float* __restrict__ out)
{
    __shared__ float sred[8];
    __shared__ float hs[DIMM];
    int b = blockIdx.x;
    int t = threadIdx.x;
    const float* row = x + (size_t)b * NTOK * DIMM;
    float a0 = row[t], a1 = row[t + 256];
    float mean = blk_sum256(a0 + a1, sred) * (1.0f / 512.0f);
    float d0 = a0 - mean, d1 = a1 - mean;
    __syncthreads();
    float var = blk_sum256(d0 * d0 + d1 * d1, sred) * (1.0f / 512.0f);
    float inv = rsqrtf(var + 1e-5f);
    hs[t]       = d0 * inv * g[t] + bb[t];
    hs[t + 256] = d1 * inv * g[t + 256] + bb[t + 256];
    __syncthreads();
    int o = blockIdx.y * 256 + t;
    if (o >= NCLS) return;
    float acc = bias[o];
    #pragma unroll 8
    for (int d = 0; d < DIMM; d++) acc += hs[d] * W[(size_t)d * NCLS + o];
    out[(size_t)b * NCLS + o] = acc;
}

// ---------------- launch ----------------
extern "C" void kernel_launch(void* const* d_in, const int* in_sizes, int n_in,
                              void* d_out, int out_size) {
    const float* img     = (const float*)d_in[0];
    const float* patch_w = (const float*)d_in[1];
    const float* patch_b = (const float*)d_in[2];
    const float* pos_emb = (const float*)d_in[3];
    const float* cls_tok = (const float*)d_in[4];
    const float* ln1_g   = (const float*)d_in[5];
    const float* ln1_b   = (const float*)d_in[6];
    const float* Wq      = (const float*)d_in[7];
    const float* Wk      = (const float*)d_in[8];
    const float* Wv      = (const float*)d_in[9];
    const float* Wg      = (const float*)d_in[10];
    const float* Wo      = (const float*)d_in[11];
    const float* kpe     = (const float*)d_in[12];
    const float* vpe     = (const float*)d_in[13];
    const float* Wkc     = (const float*)d_in[14];
    const float* Wvc     = (const float*)d_in[15];
    const float* ln2_g   = (const float*)d_in[16];
    const float* ln2_b   = (const float*)d_in[17];
    const float* ff_w1   = (const float*)d_in[18];
    const float* ff_b1   = (const float*)d_in[19];
    const float* ff_w2   = (const float*)d_in[20];
    const float* ff_b2   = (const float*)d_in[21];
    const float* hln_g   = (const float*)d_in[22];
    const float* hln_b   = (const float*)d_in[23];
    const float* head_w  = (const float*)d_in[24];
    const float* head_b  = (const float*)d_in[25];

    float *x, *h, *q, *k, *v, *gate, *ckcv, *outc, *attn, *mlp, *prt;
    int* selb;
    cudaGetSymbolAddress((void**)&x, g_x);
    cudaGetSymbolAddress((void**)&h, g_h);
    cudaGetSymbolAddress((void**)&q, g_q);
    cudaGetSymbolAddress((void**)&k, g_k);
    cudaGetSymbolAddress((void**)&v, g_v);
    cudaGetSymbolAddress((void**)&gate, g_gate);
    cudaGetSymbolAddress((void**)&ckcv, g_ckcv);
    cudaGetSymbolAddress((void**)&outc, g_outc);
    cudaGetSymbolAddress((void**)&selb, g_selb);
    cudaGetSymbolAddress((void**)&attn, g_attn);
    cudaGetSymbolAddress((void**)&mlp, g_mlp);
    cudaGetSymbolAddress((void**)&prt, g_part);

    const int CCN4 = (2 * CM * 64) / 4;
    const int CCRG = (CCN4 + 255) / 256;
    float* ck = ckcv;
    float* cv = ckcv + (size_t)CM * 64;

    // patch embed + fused ln1(layer 0)
    patch_embed_ln_kernel<<<BB * NTOK, 256>>>(img, patch_w, patch_b, pos_emb,
                                              cls_tok, ln1_g, ln1_b, x, h);

    for (int l = 0; l < 2; l++) {
        const float* Wql = Wq + (size_t)l * DIMM * DIMM;
        const float* Wkl = Wk + (size_t)l * DIMM * DIMM;
        const float* Wvl = Wv + (size_t)l * DIMM * DIMM;
        const float* Wgl = Wg + (size_t)l * DIMM * 24;
        const float* Wol = Wo + (size_t)l * DIMM * DIMM;
        const float* kpel = kpe + (size_t)l * 16 * DHH;
        const float* vpel = vpe + (size_t)l * 16 * DHH;
        const float* Wkcl = Wkc + (size_t)l * 1024 * DHH;
        const float* Wvcl = Wvc + (size_t)l * 1024 * DHH;

        qkvgW_kernel<<<dim3(13, 19), 256>>>(h, Wql, Wkl, Wvl, Wgl, q, k, v, gate);

        compress_gemm_kernel<<<dim3((CM + 63) / 64, 2, 8), 256>>>(
            k, v, kpel, vpel, Wkcl, Wvcl, prt);
        reduce4_kernel<<<CCRG, 256>>>(prt, ckcv, CCN4, 8);

        cattn_kernel<<<BB * HH * NQBA, 256>>>(q, ck, cv, outc, selb);
        swc_tile_kernel<<<BB * HH * NQT, 256>>>(q, k, v, outc, gate, selb, attn);

        gemmW_split_kernel<<<dim3(4, 19, 4), 256>>>(attn, Wol, prt, BN, DIMM, DIMM);
        reduce_ln_kernel<<<BN, 128>>>(prt, (const float*)0, x, x,
                                      ln2_g + l * DIMM, ln2_b + l * DIMM, h, 4);

        gemmW_kernel<<<dim3(16, 19), 256>>>(h, ff_w1 + (size_t)l * DIMM * MLPD,
                                            ff_b1 + (size_t)l * MLPD, (const float*)0,
                                            mlp, BN, MLPD, DIMM, ACT_GELU);

        gemmW_split_kernel<<<dim3(4, 19, 4), 256>>>(mlp, ff_w2 + (size_t)l * MLPD * DIMM,
                                                    prt, BN, DIMM, MLPD);
        if (l == 0) {
            reduce_ln_kernel<<<BN, 128>>>(prt, ff_b2, x, x,
                                          ln1_g + DIMM, ln1_b + DIMM, h, 4);
        } else {
            reduce_ln_kernel<<<BN, 128>>>(prt, ff_b2 + (size_t)l * DIMM, x, x,
                                          (const float*)0, (const float*)0, h, 4);
        }
    }

    head_ln_kernel<<<dim3(BB, (NCLS + 255) / 256), 256>>>(
        x, hln_g, hln_b, head_w, head_b, (float*)d_out);
}

// round 16
// speedup vs baseline: 1.1142x; 1.0124x over previous
#include <cuda_runtime.h>
#include <math.h>

// ---------------- problem constants ----------------
#define BB   2
#define NTOK 577
#define DIMM 512
#define HH   8
#define DHH  64
#define NCC  145
#define NSB  10
#define KSEL 4
#define SWIN 32
#define MLPD 2048
#define NCLS 1000
#define BN   (BB*NTOK)    // 1154
#define QCA  12
#define NQBA 49
#define CM   (BB*HH*NCC)  // 2320
#define QT   16
#define NQT  37
#define PARTSZ (16*CM*64)

#define ACT_NONE 0
#define ACT_GELU 1
#define ACT_SIG  2

// ---------------- device scratch ----------------
__device__ float g_x   [BN*DIMM];
__device__ float g_h   [BN*DIMM];
__device__ float g_q   [BN*DIMM];
__device__ float g_k   [BN*DIMM];
__device__ float g_v   [BN*DIMM];
__device__ float g_gate[BN*24];
__device__ float g_ckcv[2*CM*DHH];
__device__ float g_outc[BB*HH*NTOK*DHH];
__device__ int   g_selb[BB*HH*NTOK*KSEL];
__device__ float g_attn[BN*DIMM];
__device__ float g_mlp [BN*MLPD];
__device__ float g_part[PARTSZ];

// ---------------- helpers ----------------
__device__ __forceinline__ float gelu_tanh(float x) {
    float x3 = x * x * x;
    return 0.5f * x * (1.0f + tanhf(0.7978845608028654f * (x + 0.044715f * x3)));
}

__device__ __forceinline__ float blk_sum256(float v, float* sred) {
    #pragma unroll
    for (int o = 16; o; o >>= 1) v += __shfl_xor_sync(0xffffffffu, v, o);
    __syncthreads();
    if ((threadIdx.x & 31) == 0) sred[threadIdx.x >> 5] = v;
    __syncthreads();
    float r = sred[0];
    #pragma unroll
    for (int w = 1; w < 8; w++) r += sred[w];
    return r;
}
__device__ __forceinline__ float blk_sum128(float v, float* sred) {
    #pragma unroll
    for (int o = 16; o; o >>= 1) v += __shfl_xor_sync(0xffffffffu, v, o);
    __syncthreads();
    if ((threadIdx.x & 31) == 0) sred[threadIdx.x >> 5] = v;
    __syncthreads();
    return sred[0] + sred[1] + sred[2] + sred[3];
}

// ---------------- patch embed + cls + pos + fused LN1(layer0) ----------------
__global__ __launch_bounds__(256) void patch_embed_ln_kernel(
    const float* __restrict__ img, const float* __restrict__ pw,
    const float* __restrict__ pb, const float* __restrict__ pos,
    const float* __restrict__ cls,
    const float* __restrict__ g, const float* __restrict__ bb,
    float* __restrict__ x, float* __restrict__ h)
{
    __shared__ float sred[8];
    int t = blockIdx.x % NTOK;
    int b = blockIdx.x / NTOK;
    int tid = threadIdx.x;
    float val[2];
    #pragma unroll
    for (int half = 0; half < 2; half++) {
        int d = tid + half * 256;
        float v;
        if (t == 0) {
            v = cls[d];
        } else {
            int p = t - 1;
            int ii = p / 24, jj = p % 24;
            v = pb[d];
            #pragma unroll
            for (int c = 0; c < 3; c++)
                v += img[((b * 3 + c) * 24 + ii) * 24 + jj] * pw[c * DIMM + d];
        }
        val[half] = v + pos[(size_t)t * DIMM + d];
    }
    size_t off = (size_t)(b * NTOK + t) * DIMM;
    x[off + tid]       = val[0];
    x[off + tid + 256] = val[1];
    float mean = blk_sum256(val[0] + val[1], sred) * (1.0f / 512.0f);
    float d0 = val[0] - mean, d1 = val[1] - mean;
    __syncthreads();
    float var = blk_sum256(d0 * d0 + d1 * d1, sred) * (1.0f / 512.0f);
    float inv = rsqrtf(var + 1e-5f);
    h[off + tid]       = d0 * inv * g[tid] + bb[tid];
    h[off + tid + 256] = d1 * inv * g[tid + 256] + bb[tid + 256];
}

// ---------------- SGEMM core A: 64x64 tile, 4x4/thread ----------------
__device__ __forceinline__ void gemm_core(
    const float* __restrict__ A, const float* __restrict__ W,
    const float* __restrict__ bias, const float* __restrict__ res,
    float* __restrict__ C, float* __restrict__ part,
    int M, int Nn, int K, int act, int row0, int col0, int k0, int kLen)
{
    __shared__ __align__(16) float As[2][16][68];
    __shared__ __align__(16) float Bs[2][16][64];
    int tid = threadIdx.x;
    int tx = tid & 15, ty = tid >> 4;

    int am  = tid >> 2;
    int akq = tid & 3;
    int arow = row0 + am;
    const float* Aptr = (arow < M) ? (A + (size_t)arow * K + k0 + akq * 4) : (const float*)0;
    int bkk = tid >> 4;
    int bnq = tid & 15;
    int bcol = col0 + bnq * 4;
    const float* Wptr = W + (size_t)(k0 + bkk) * Nn + bcol;
    bool bfull = (bcol + 3 < Nn);
    bool bany  = (bcol < Nn);

    float4 a4, b4;
    if (Aptr) a4 = *(const float4*)(Aptr);
    else      a4 = make_float4(0.f, 0.f, 0.f, 0.f);
    if (bfull) b4 = *(const float4*)(Wptr);
    else {
        b4 = make_float4(0.f, 0.f, 0.f, 0.f);
        if (bany) {
            b4.x = Wptr[0];
            if (bcol + 1 < Nn) b4.y = Wptr[1];
            if (bcol + 2 < Nn) b4.z = Wptr[2];
        }
    }
    As[0][akq * 4 + 0][am] = a4.x;
    As[0][akq * 4 + 1][am] = a4.y;
    As[0][akq * 4 + 2][am] = a4.z;
    As[0][akq * 4 + 3][am] = a4.w;
    *(float4*)&Bs[0][bkk][bnq * 4] = b4;
    __syncthreads();

    float acc[4][4];
    #pragma unroll
    for (int i = 0; i < 4; i++)
        #pragma unroll
        for (int j = 0; j < 4; j++) acc[i][j] = 0.f;

    int steps = kLen >> 4;
    for (int ks = 0; ks < steps; ks++) {
        int cur = ks & 1;
        bool hn = (ks + 1 < steps);
        if (hn) {
            int kk0 = (ks + 1) * 16;
            if (Aptr) a4 = *(const float4*)(Aptr + kk0);
            else      a4 = make_float4(0.f, 0.f, 0.f, 0.f);
            if (bfull) b4 = *(const float4*)(Wptr + (size_t)kk0 * Nn);
            else {
                b4 = make_float4(0.f, 0.f, 0.f, 0.f);
                if (bany) {
                    const float* p = Wptr + (size_t)kk0 * Nn;
                    b4.x = p[0];
                    if (bcol + 1 < Nn) b4.y = p[1];
                    if (bcol + 2 < Nn) b4.z = p[2];
                }
            }
        }
        #pragma unroll
        for (int kk = 0; kk < 16; kk++) {
            float4 av = *(const float4*)&As[cur][kk][ty * 4];
            float4 bv = *(const float4*)&Bs[cur][kk][tx * 4];
            acc[0][0] += av.x * bv.x; acc[0][1] += av.x * bv.y; acc[0][2] += av.x * bv.z; acc[0][3] += av.x * bv.w;
            acc[1][0] += av.y * bv.x; acc[1][1] += av.y * bv.y; acc[1][2] += av.y * bv.z; acc[1][3] += av.y * bv.w;
            acc[2][0] += av.z * bv.x; acc[2][1] += av.z * bv.y; acc[2][2] += av.z * bv.z; acc[2][3] += av.z * bv.w;
            acc[3][0] += av.w * bv.x; acc[3][1] += av.w * bv.y; acc[3][2] += av.w * bv.z; acc[3][3] += av.w * bv.w;
        }
        if (hn) {
            int nxt = cur ^ 1;
            As[nxt][akq * 4 + 0][am] = a4.x;
            As[nxt][akq * 4 + 1][am] = a4.y;
            As[nxt][akq * 4 + 2][am] = a4.z;
            As[nxt][akq * 4 + 3][am] = a4.w;
            *(float4*)&Bs[nxt][bkk][bnq * 4] = b4;
            __syncthreads();
        }
    }
    #pragma unroll
    for (int i = 0; i < 4; i++) {
        int r = row0 + ty * 4 + i;
        if (r >= M) continue;
        #pragma unroll
        for (int j = 0; j < 4; j++) {
            int c = col0 + tx * 4 + j;
            if (c >= Nn) continue;
            float v = acc[i][j];
            size_t off = (size_t)r * Nn + c;
            if (part) {
                part[off] = v;
            } else {
                if (bias) v += bias[c];
                if (act == ACT_GELU) v = gelu_tanh(v);
                else if (act == ACT_SIG) v = 1.0f / (1.0f + expf(-v));
                if (res) v += res[off];
                C[off] = v;
            }
        }
    }
}

// ---------------- SGEMM core B: 64x128 tile, 4x8/thread ----------------
__device__ __forceinline__ void gemmW_core(
    const float* __restrict__ A, const float* __restrict__ W,
    const float* __restrict__ bias, const float* __restrict__ res,
    float* __restrict__ C, float* __restrict__ part,
    int M, int Nn, int K, int act, int row0, int col0, int k0, int kLen)
{
    __shared__ __align__(16) float As[2][16][68];
    __shared__ __align__(16) float Bs[2][16][128];
    int tid = threadIdx.x;
    int tx = tid & 15, ty = tid >> 4;

    int am  = tid >> 2;
    int akq = tid & 3;
    int arow = row0 + am;
    const float* Aptr = (arow < M) ? (A + (size_t)arow * K + k0 + akq * 4) : (const float*)0;
    int bkk = tid >> 4;
    int bnq = tid & 15;
    const float* Wptr = W + (size_t)(k0 + bkk) * Nn + col0 + bnq * 4;

    float4 a4, b4a, b4b;
    if (Aptr) a4 = *(const float4*)(Aptr);
    else      a4 = make_float4(0.f, 0.f, 0.f, 0.f);
    b4a = *(const float4*)(Wptr);
    b4b = *(const float4*)(Wptr + 64);
    As[0][akq * 4 + 0][am] = a4.x;
    As[0][akq * 4 + 1][am] = a4.y;
    As[0][akq * 4 + 2][am] = a4.z;
    As[0][akq * 4 + 3][am] = a4.w;
    *(float4*)&Bs[0][bkk][bnq * 4]      = b4a;
    *(float4*)&Bs[0][bkk][64 + bnq * 4] = b4b;
    __syncthreads();

    float acc[4][8];
    #pragma unroll
    for (int i = 0; i < 4; i++)
        #pragma unroll
        for (int j = 0; j < 8; j++) acc[i][j] = 0.f;

    int steps = kLen >> 4;
    for (int ks = 0; ks < steps; ks++) {
        int cur = ks & 1;
        bool hn = (ks + 1 < steps);
        if (hn) {
            int kk0 = (ks + 1) * 16;
            if (Aptr) a4 = *(const float4*)(Aptr + kk0);
            else      a4 = make_float4(0.f, 0.f, 0.f, 0.f);
            const float* p = Wptr + (size_t)kk0 * Nn;
            b4a = *(const float4*)(p);
            b4b = *(const float4*)(p + 64);
        }
        #pragma unroll
        for (int kk = 0; kk < 16; kk++) {
            float4 av = *(const float4*)&As[cur][kk][ty * 4];
            float4 bv0 = *(const float4*)&Bs[cur][kk][tx * 4];
            float4 bv1 = *(const float4*)&Bs[cur][kk][64 + tx * 4];
            float a0 = av.x, a1 = av.y, a2 = av.z, a3 = av.w;
            acc[0][0] += a0 * bv0.x; acc[0][1] += a0 * bv0.y; acc[0][2] += a0 * bv0.z; acc[0][3] += a0 * bv0.w;
            acc[0][4] += a0 * bv1.x; acc[0][5] += a0 * bv1.y; acc[0][6] += a0 * bv1.z; acc[0][7] += a0 * bv1.w;
            acc[1][0] += a1 * bv0.x; acc[1][1] += a1 * bv0.y; acc[1][2] += a1 * bv0.z; acc[1][3] += a1 * bv0.w;
            acc[1][4] += a1 * bv1.x; acc[1][5] += a1 * bv1.y; acc[1][6] += a1 * bv1.z; acc[1][7] += a1 * bv1.w;
            acc[2][0] += a2 * bv0.x; acc[2][1] += a2 * bv0.y; acc[2][2] += a2 * bv0.z; acc[2][3] += a2 * bv0.w;
            acc[2][4] += a2 * bv1.x; acc[2][5] += a2 * bv1.y; acc[2][6] += a2 * bv1.z; acc[2][7] += a2 * bv1.w;
            acc[3][0] += a3 * bv0.x; acc[3][1] += a3 * bv0.y; acc[3][2] += a3 * bv0.z; acc[3][3] += a3 * bv0.w;
            acc[3][4] += a3 * bv1.x; acc[3][5] += a3 * bv1.y; acc[3][6] += a3 * bv1.z; acc[3][7] += a3 * bv1.w;
        }
        if (hn) {
            int nxt = cur ^ 1;
            As[nxt][akq * 4 + 0][am] = a4.x;
            As[nxt][akq * 4 + 1][am] = a4.y;
            As[nxt][akq * 4 + 2][am] = a4.z;
            As[nxt][akq * 4 + 3][am] = a4.w;
            *(float4*)&Bs[nxt][bkk][bnq * 4]      = b4a;
            *(float4*)&Bs[nxt][bkk][64 + bnq * 4] = b4b;
            __syncthreads();
        }
    }
    #pragma unroll
    for (int i = 0; i < 4; i++) {
        int r = row0 + ty * 4 + i;
        if (r >= M) continue;
        #pragma unroll
        for (int half = 0; half < 2; half++) {
            int c = col0 + half * 64 + tx * 4;
            size_t off = (size_t)r * Nn + c;
            float4 v;
            v.x = acc[i][half * 4 + 0]; v.y = acc[i][half * 4 + 1];
            v.z = acc[i][half * 4 + 2]; v.w = acc[i][half * 4 + 3];
            if (part) {
                *(float4*)(part + off) = v;
            } else {
                if (bias) {
                    v.x += bias[c]; v.y += bias[c + 1];
                    v.z += bias[c + 2]; v.w += bias[c + 3];
                }
                if (act == ACT_GELU) {
                    v.x = gelu_tanh(v.x); v.y = gelu_tanh(v.y);
                    v.z = gelu_tanh(v.z); v.w = gelu_tanh(v.w);
                }
                if (res) {
                    float4 r4 = *(const float4*)(res + off);
                    v.x += r4.x; v.y += r4.y; v.z += r4.z; v.w += r4.w;
                }
                *(float4*)(C + off) = v;
            }
        }
    }
}

__global__ __launch_bounds__(256) void gemmW_kernel(
    const float* __restrict__ A, const float* __restrict__ W,
    const float* __restrict__ bias, const float* __restrict__ res,
    float* __restrict__ C, int M, int Nn, int K, int act)
{
    gemmW_core(A, W, bias, res, C, (float*)0, M, Nn, K, act,
               blockIdx.y * 64, blockIdx.x * 128, 0, K);
}

__global__ __launch_bounds__(256) void gemmW_split_kernel(
    const float* __restrict__ A, const float* __restrict__ W,
    float* __restrict__ part, int M, int Nn, int K)
{
    int chunk = K / gridDim.z;
    float* p = part + (size_t)blockIdx.z * M * Nn;
    gemmW_core(A, W, (const float*)0, (const float*)0, (float*)0, p,
               M, Nn, K, ACT_NONE,
               blockIdx.y * 64, blockIdx.x * 128, blockIdx.z * chunk, chunk);
}

// fused QKV (64x128 core) + gate (64x64 core)
__global__ __launch_bounds__(256) void qkvgW_kernel(
    const float* __restrict__ h,
    const float* __restrict__ Wq, const float* __restrict__ Wk,
    const float* __restrict__ Wv, const float* __restrict__ Wg,
    float* __restrict__ q, float* __restrict__ k,
    float* __restrict__ v, float* __restrict__ gate)
{
    int bx = blockIdx.x;
    if (bx < 12) {
        int sel = bx >> 2;
        const float* W; float* C;
        if (sel == 0)      { W = Wq; C = q; }
        else if (sel == 1) { W = Wk; C = k; }
        else               { W = Wv; C = v; }
        gemmW_core(h, W, (const float*)0, (const float*)0, C, (float*)0,
                   BN, DIMM, DIMM, ACT_NONE, blockIdx.y * 64, (bx & 3) * 128, 0, DIMM);
    } else {
        gemm_core(h, Wg, (const float*)0, (const float*)0, gate, (float*)0,
                  BN, 24, DIMM, ACT_SIG, blockIdx.y * 64, 0, 0, DIMM);
    }
}

// ---------------- fused split-K reduce + residual + LayerNorm ----------------
__global__ __launch_bounds__(128) void reduce_ln_kernel(
    const float* __restrict__ part, const float* __restrict__ bias,
    const float* __restrict__ res, float* __restrict__ x,
    const float* __restrict__ gamma, const float* __restrict__ beta,
    float* __restrict__ h, int S)
{
    __shared__ float sred[4];
    int r = blockIdx.x;
    int t = threadIdx.x;
    int c = t * 4;
    size_t off = (size_t)r * DIMM + c;
    size_t stride = (size_t)BN * DIMM;
    float4 s = *(const float4*)(part + off);
    for (int i = 1; i < S; i++) {
        float4 p = *(const float4*)(part + (size_t)i * stride + off);
        s.x += p.x; s.y += p.y; s.z += p.z; s.w += p.w;
    }
    if (bias) {
        s.x += bias[c]; s.y += bias[c + 1]; s.z += bias[c + 2]; s.w += bias[c + 3];
    }
    if (res) {
        float4 r4 = *(const float4*)(res + off);
        s.x += r4.x; s.y += r4.y; s.z += r4.z; s.w += r4.w;
    }
    *(float4*)(x + off) = s;
    if (!gamma) return;
    float mean = blk_sum128(s.x + s.y + s.z + s.w, sred) * (1.0f / 512.0f);
    float d0 = s.x - mean, d1 = s.y - mean, d2 = s.z - mean, d3 = s.w - mean;
    __syncthreads();
    float var = blk_sum128(d0 * d0 + d1 * d1 + d2 * d2 + d3 * d3, sred) * (1.0f / 512.0f);
    float inv = rsqrtf(var + 1e-5f);
    float4 o;
    o.x = d0 * inv * gamma[c]     + beta[c];
    o.y = d1 * inv * gamma[c + 1] + beta[c + 1];
    o.z = d2 * inv * gamma[c + 2] + beta[c + 2];
    o.w = d3 * inv * gamma[c + 3] + beta[c + 3];
    *(float4*)(h + off) = o;
}

// specialized S=8 split-K reduce (compress path): 8 independent loads, tree sum
__global__ __launch_bounds__(256) void reduce8_kernel(
    const float* __restrict__ part, float* __restrict__ C, int MN4)
{
    int idx = blockIdx.x * 256 + threadIdx.x;
    if (idx >= MN4) return;
    size_t off = (size_t)idx * 4;
    size_t stride = (size_t)MN4 * 4;
    float4 p0 = *(const float4*)(part + off);
    float4 p1 = *(const float4*)(part + stride + off);
    float4 p2 = *(const float4*)(part + 2 * stride + off);
    float4 p3 = *(const float4*)(part + 3 * stride + off);
    float4 p4 = *(const float4*)(part + 4 * stride + off);
    float4 p5 = *(const float4*)(part + 5 * stride + off);
    float4 p6 = *(const float4*)(part + 6 * stride + off);
    float4 p7 = *(const float4*)(part + 7 * stride + off);
    float4 s;
    s.x = ((p0.x + p1.x) + (p2.x + p3.x)) + ((p4.x + p5.x) + (p6.x + p7.x));
    s.y = ((p0.y + p1.y) + (p2.y + p3.y)) + ((p4.y + p5.y) + (p6.y + p7.y));
    s.z = ((p0.z + p1.z) + (p2.z + p3.z)) + ((p4.z + p5.z) + (p6.z + p7.z));
    s.w = ((p0.w + p1.w) + (p2.w + p3.w)) + ((p4.w + p5.w) + (p6.w + p7.w));
    *(float4*)(C + off) = s;
}

// ---------------- compress as gather-A GEMM, split-K x8 ----------------
__global__ __launch_bounds__(256) void compress_gemm_kernel(
    const float* __restrict__ kin, const float* __restrict__ vin,
    const float* __restrict__ kpe, const float* __restrict__ vpe,
    const float* __restrict__ Wkc, const float* __restrict__ Wvc,
    float* __restrict__ part)
{
    const float* in; const float* pe; const float* Wc;
    if (blockIdx.y == 0) { in = kin; pe = kpe; Wc = Wkc; }
    else                 { in = vin; pe = vpe; Wc = Wvc; }
    float* out = part + ((size_t)(blockIdx.z * 2 + blockIdx.y)) * CM * 64;
    int k0 = blockIdx.z * 128;

    __shared__ __align__(16) float As[2][16][68];
    __shared__ __align__(16) float Bs[2][16][64];
    int tid = threadIdx.x;
    int tx = tid & 15, ty = tid >> 4;
    int row0 = blockIdx.x * 64;

    int am  = tid >> 2;
    int akq = tid & 3;
    int row = row0 + am;
    bool avalid = row < CM;
    int rr = avalid ? row : CM - 1;
    int bh = rr / NCC, j = rr - bh * NCC;
    int b = bh >> 3, hh = bh & 7;
    const float* kb = in + (size_t)b * NTOK * DIMM + hh * DHH;
    int j4 = j * 4;

    auto fetchA = [&](int e) -> float4 {
        float4 p = *(const float4*)(pe + e);
        int jj = e >> 6, d = e & 63;
        int tok = j4 + jj;
        if (tok < NTOK) {
            float4 kv = *(const float4*)(kb + (size_t)tok * DIMM + d);
            p.x += kv.x; p.y += kv.y; p.z += kv.z; p.w += kv.w;
        }
        return p;
    };

    int bkk = tid >> 4;
    int bnq = tid & 15;
    const float* Wptr = Wc + (size_t)(k0 + bkk) * 64 + bnq * 4;

    float4 a4 = avalid ? fetchA(k0 + akq * 4) : make_float4(0.f, 0.f, 0.f, 0.f);
    float4 b4 = *(const float4*)(Wptr);
    As[0][akq * 4 + 0][am] = a4.x;
    As[0][akq * 4 + 1][am] = a4.y;
    As[0][akq * 4 + 2][am] = a4.z;
    As[0][akq * 4 + 3][am] = a4.w;
    *(float4*)&Bs[0][bkk][bnq * 4] = b4;
    __syncthreads();

    float acc[4][4];
    #pragma unroll
    for (int i = 0; i < 4; i++)
        #pragma unroll
        for (int jq = 0; jq < 4; jq++) acc[i][jq] = 0.f;

    const int steps = 8;
    for (int ks = 0; ks < steps; ks++) {
        int cur = ks & 1;
        bool hn = (ks + 1 < steps);
        if (hn) {
            int e = k0 + (ks + 1) * 16 + akq * 4;
            a4 = avalid ? fetchA(e) : make_float4(0.f, 0.f, 0.f, 0.f);
            b4 = *(const float4*)(Wptr + (size_t)(ks + 1) * 16 * 64);
        }
        #pragma unroll
        for (int kk = 0; kk < 16; kk++) {
            float4 av = *(const float4*)&As[cur][kk][ty * 4];
            float4 bv = *(const float4*)&Bs[cur][kk][tx * 4];
            acc[0][0] += av.x * bv.x; acc[0][1] += av.x * bv.y; acc[0][2] += av.x * bv.z; acc[0][3] += av.x * bv.w;
            acc[1][0] += av.y * bv.x; acc[1][1] += av.y * bv.y; acc[1][2] += av.y * bv.z; acc[1][3] += av.y * bv.w;
            acc[2][0] += av.z * bv.x; acc[2][1] += av.z * bv.y; acc[2][2] += av.z * bv.z; acc[2][3] += av.z * bv.w;
            acc[3][0] += av.w * bv.x; acc[3][1] += av.w * bv.y; acc[3][2] += av.w * bv.z; acc[3][3] += av.w * bv.w;
        }
        if (hn) {
            int nxt = cur ^ 1;
            As[nxt][akq * 4 + 0][am] = a4.x;
            As[nxt][akq * 4 + 1][am] = a4.y;
            As[nxt][akq * 4 + 2][am] = a4.z;
            As[nxt][akq * 4 + 3][am] = a4.w;
            *(float4*)&Bs[nxt][bkk][bnq * 4] = b4;
            __syncthreads();
        }
    }
    #pragma unroll
    for (int i = 0; i < 4; i++) {
        int r = row0 + ty * 4 + i;
        if (r >= CM) continue;
        int c = tx * 4;
        *(float4*)(out + (size_t)r * 64 + c) =
            make_float4(acc[i][0], acc[i][1], acc[i][2], acc[i][3]);
    }
}

// ---------------- compressed attention + top-k (12 queries/block) ----------------
__global__ __launch_bounds__(256) void cattn_kernel(
    const float* __restrict__ q, const float* __restrict__ ck,
    const float* __restrict__ cv, float* __restrict__ outc,
    int* __restrict__ selb)
{
    __shared__ float cbuf[NCC * 65];
    __shared__ float qs[QCA * 64];
    __shared__ float sc[QCA][NCC];
    int blk = blockIdx.x;
    int qb = blk % NQBA, bh = blk / NQBA;
    int h = bh % HH, b = bh / HH;
    int i0 = qb * QCA;
    int tid = threadIdx.x;
    for (int idx = tid; idx < QCA * 64; idx += 256) {
        int u = idx >> 6, d2 = idx & 63, i = i0 + u;
        qs[idx] = (i < NTOK) ? q[((size_t)(b * NTOK + i)) * DIMM + h * DHH + d2] : 0.f;
    }
    const float* ckb = ck + (size_t)bh * NCC * DHH;
    for (int idx = tid; idx < NCC * 64; idx += 256) {
        int j = idx >> 6, d2 = idx & 63;
        cbuf[j * 65 + d2] = ckb[idx];
    }
    __syncthreads();
    for (int p = tid; p < QCA * NCC; p += 256) {
        int u = p / NCC, j = p % NCC;
        const float* cr = &cbuf[j * 65];
        const float* qr = &qs[u * 64];
        float a = 0.f;
        #pragma unroll
        for (int d2 = 0; d2 < 64; d2++) a += qr[d2] * cr[d2];
        sc[u][j] = a * 0.125f;
    }
    __syncthreads();
    int w = tid >> 5, ln = tid & 31;
    for (int u = w; u < QCA; u += 8) {
        float m = -1e30f;
        for (int j = ln; j < NCC; j += 32) m = fmaxf(m, sc[u][j]);
        #pragma unroll
        for (int o = 16; o; o >>= 1) m = fmaxf(m, __shfl_xor_sync(0xffffffffu, m, o));
        float s = 0.f;
        for (int j = ln; j < NCC; j += 32) { float e = expf(sc[u][j] - m); sc[u][j] = e; s += e; }
        #pragma unroll
        for (int o = 16; o; o >>= 1) s += __shfl_xor_sync(0xffffffffu, s, o);
        float inv = 1.f / s;
        for (int j = ln; j < NCC; j += 32) sc[u][j] *= inv;
    }
    __syncthreads();
    if (tid < QCA) {
        int i = i0 + tid;
        if (i < NTOK) {
            float imp[NSB];
            #pragma unroll
            for (int t = 0; t < NSB; t++) imp[t] = 0.f;
            for (int j = 0; j < NCC; j++) {
                int c = (j + 2) >> 4; if (c > NSB - 1) c = NSB - 1;
                imp[c] += sc[tid][j];
            }
            size_t gi = (size_t)bh * NTOK + i;
            #pragma unroll
            for (int t = 0; t < KSEL; t++) {
                float best = -1e30f; int bi = 0;
                #pragma unroll
                for (int sbv = 0; sbv < NSB; sbv++)
                    if (imp[sbv] > best) { best = imp[sbv]; bi = sbv; }
                selb[gi * KSEL + t] = bi;
                imp[bi] = -2e30f;
            }
        }
    }
    __syncthreads();
    const float* cvb = cv + (size_t)bh * NCC * DHH;
    for (int idx = tid; idx < NCC * 64; idx += 256) {
        int j = idx >> 6, d2 = idx & 63;
        cbuf[j * 65 + d2] = cvb[idx];
    }
    __syncthreads();
    // PV: register-blocked over 3 queries per thread group
    {
        int grp = tid >> 6, d2 = tid & 63;
        int u0 = grp * 3;
        float a0 = 0.f, a1 = 0.f, a2 = 0.f;
        for (int j = 0; j < NCC; j++) {
            float cvv = cbuf[j * 65 + d2];
            a0 += sc[u0][j] * cvv;
            a1 += sc[u0 + 1][j] * cvv;
            a2 += sc[u0 + 2][j] * cvv;
        }
        float av[3] = {a0, a1, a2};
        #pragma unroll
        for (int e = 0; e < 3; e++) {
            int i = i0 + u0 + e;
            if (i < NTOK)
                outc[((size_t)(bh * NTOK + i)) * 64 + d2] = av[e];
        }
    }
}

// ==== tiled: selected-block attn + sliding window + gate combine (16 q/block) ====
__global__ __launch_bounds__(256) void swc_tile_kernel(
    const float* __restrict__ q, const float* __restrict__ k,
    const float* __restrict__ v, const float* __restrict__ outc,
    const float* __restrict__ gate, const int* __restrict__ selb,
    float* __restrict__ attn)
{
    __shared__ float qs[QT * 64];
    __shared__ float kvb[64 * 65];
    __shared__ float ss[QT][256];
    __shared__ float pw[QT][33];
    __shared__ int   sb[QT][4];
    __shared__ unsigned smask;

    int bx = blockIdx.x;
    int qt = bx % NQT;
    int bh = bx / NQT;
    int hd = bh % HH, b = bh / HH;
    int i0 = qt * QT;
    int tid = threadIdx.x;
    int lane = tid & 31, w = tid >> 5;

    for (int idx = tid; idx < QT * 64; idx += 256) {
        int u = idx >> 6, d = idx & 63;
        int i = i0 + u;
        qs[idx] = (i < NTOK) ? q[((size_t)(b * NTOK + i)) * DIMM + hd * DHH + d] : 0.f;
    }
    if (tid == 0) smask = 0;
    if (tid < QT * 4) {
        int u = tid >> 2, c = tid & 3;
        int i = i0 + u;
        sb[u][c] = (i < NTOK) ? selb[((size_t)(bh * NTOK + i)) * KSEL + c] : -1;
    }
    __syncthreads();
    if (tid < QT * 4) {
        int s = sb[tid >> 2][tid & 3];
        if (s >= 0) atomicOr(&smask, 1u << s);
    }
    __syncthreads();
    unsigned mask = smask;

    const float* kbase = k + (size_t)b * NTOK * DIMM + hd * DHH;
    const float* vbase = v + (size_t)b * NTOK * DIMM + hd * DHH;

    for (int sblk = 0; sblk < NSB; sblk++) {
        if (!((mask >> sblk) & 1u)) continue;
        for (int idx = tid; idx < 4096; idx += 256) {
            int t = idx >> 6, d = idx & 63;
            int tok = sblk * 64 + t; int tk = tok < NTOK ? tok : NTOK - 1;
            kvb[t * 65 + d] = kbase[(size_t)tk * DIMM + d];
        }
        __syncthreads();
        #pragma unroll
        for (int uu = 0; uu < 2; uu++) {
            int u = w * 2 + uu;
            #pragma unroll
            for (int c = 0; c < 4; c++) {
                if (sb[u][c] != sblk) continue;
                const float* qr = &qs[u * 64];
                #pragma unroll
                for (int tt = 0; tt < 2; tt++) {
                    int t = lane + tt * 32;
                    const float* kr = &kvb[t * 65];
                    float a = 0.f;
                    #pragma unroll
                    for (int d = 0; d < 64; d++) a += qr[d] * kr[d];
                    int tok = sblk * 64 + t;
                    ss[u][c * 64 + t] = (tok < NTOK) ? a * 0.125f : -1e30f;
                }
            }
        }
        __syncthreads();
    }

    #pragma unroll
    for (int uu = 0; uu < 2; uu++) {
        int u = w * 2 + uu;
        if (i0 + u < NTOK) {
            float m = -1e30f;
            #pragma unroll
            for (int j = 0; j < 8; j++) m = fmaxf(m, ss[u][lane + j * 32]);
            #pragma unroll
            for (int o = 16; o; o >>= 1) m = fmaxf(m, __shfl_xor_sync(0xffffffffu, m, o));
            float s = 0.f;
            #pragma unroll
            for (int j = 0; j < 8; j++) {
                float e = expf(ss[u][lane + j * 32] - m);
                ss[u][lane + j * 32] = e; s += e;
            }
            #pragma unroll
            for (int o = 16; o; o >>= 1) s += __shfl_xor_sync(0xffffffffu, s, o);
            float inv = 1.f / s;
            #pragma unroll
            for (int j = 0; j < 8; j++) ss[u][lane + j * 32] *= inv;
        }
    }
    __syncthreads();

    float accs[2][2] = {{0.f, 0.f}, {0.f, 0.f}};
    for (int sblk = 0; sblk < NSB; sblk++) {
        if (!((mask >> sblk) & 1u)) continue;
        for (int idx = tid; idx < 4096; idx += 256) {
            int t = idx >> 6, d = idx & 63;
            int tok = sblk * 64 + t; int tk = tok < NTOK ? tok : NTOK - 1;
            kvb[t * 65 + d] = vbase[(size_t)tk * DIMM + d];
        }
        __syncthreads();
        #pragma unroll
        for (int uu = 0; uu < 2; uu++) {
            int u = w * 2 + uu;
            #pragma unroll
            for (int c = 0; c < 4; c++) {
                if (sb[u][c] != sblk) continue;
                const float* pr = &ss[u][c * 64];
                for (int t = 0; t < 64; t++) {
                    float p = pr[t];
                    accs[uu][0] += p * kvb[t * 65 + lane];
                    accs[uu][1] += p * kvb[t * 65 + lane + 32];
                }
            }
        }
        __syncthreads();
    }

    const int WROWS = QT + SWIN - 1;
    int base = i0 - SWIN / 2;
    for (int idx = tid; idx < WROWS * 64; idx += 256) {
        int r = idx >> 6, d = idx & 63;
        int pos = base + r; int p = pos < 0 ? 0 : (pos > NTOK - 1 ? NTOK - 1 : pos);
        kvb[r * 65 + d] = kbase[(size_t)p * DIMM + d];
    }
    __syncthreads();
    #pragma unroll
    for (int uu = 0; uu < 2; uu++) {
        int u = w * 2 + uu;
        int i = i0 + u;
        int pos = i + lane - SWIN / 2;
        bool valid = (i < NTOK) && pos >= 0 && pos < NTOK;
        int r = u + lane;
        const float* qr = &qs[u * 64];
        const float* kr = &kvb[r * 65];
        float a = 0.f;
        #pragma unroll
        for (int d = 0; d < 64; d++) a += qr[d] * kr[d];
        float s = valid ? a * 0.125f : -1e30f;
        float m = s;
        #pragma unroll
        for (int o = 16; o; o >>= 1) m = fmaxf(m, __shfl_xor_sync(0xffffffffu, m, o));
        float e = expf(s - m);
        float t = e;
        #pragma unroll
        for (int o = 16; o; o >>= 1) t += __shfl_xor_sync(0xffffffffu, t, o);
        pw[u][lane] = e / t;
    }
    __syncthreads();
    for (int idx = tid; idx < WROWS * 64; idx += 256) {
        int r = idx >> 6, d = idx & 63;
        int pos = base + r; int p = pos < 0 ? 0 : (pos > NTOK - 1 ? NTOK - 1 : pos);
        kvb[r * 65 + d] = vbase[(size_t)p * DIMM + d];
    }
    __syncthreads();
    float accw[2][2] = {{0.f, 0.f}, {0.f, 0.f}};
    #pragma unroll
    for (int uu = 0; uu < 2; uu++) {
        int u = w * 2 + uu;
        for (int ww = 0; ww < SWIN; ww++) {
            float p = pw[u][ww];
            accw[uu][0] += p * kvb[(u + ww) * 65 + lane];
            accw[uu][1] += p * kvb[(u + ww) * 65 + lane + 32];
        }
    }

    #pragma unroll
    for (int uu = 0; uu < 2; uu++) {
        int u = w * 2 + uu;
        int i = i0 + u;
        if (i >= NTOK) continue;
        int row = b * NTOK + i;
        const float* gp = gate + (size_t)row * 24 + hd * 3;
        float g0 = gp[0], g1 = gp[1], g2 = gp[2];
        size_t gi = (size_t)bh * NTOK + i;
        #pragma unroll
        for (int dd = 0; dd < 2; dd++) {
            int d = lane + dd * 32;
            attn[(size_t)row * DIMM + hd * DHH + d] =
                g0 * outc[gi * 64 + d] + g1 * accs[uu][dd] + g2 * accw[uu][dd];
        }
    }
}

// ---------------- fused final LN + classifier head ----------------
__global__ __launch_bounds__(256) void head_ln_kernel(
    const float* __restrict__ x, const float* __restrict__ g,
    const float* __restrict__ bb, const float* __restrict__ W,
    const float* __restrict__ bias, float* __restrict__ out)
{
    __shared__ float sred[8];
    __shared__ float hs[DIMM];
    int b = blockIdx.x;
    int t = threadIdx.x;
    const float* row = x + (size_t)b * NTOK * DIMM;
    float a0 = row[t], a1 = row[t + 256];
    float mean = blk_sum256(a0 + a1, sred) * (1.0f / 512.0f);
    float d0 = a0 - mean, d1 = a1 - mean;
    __syncthreads();
    float var = blk_sum256(d0 * d0 + d1 * d1, sred) * (1.0f / 512.0f);
    float inv = rsqrtf(var + 1e-5f);
    hs[t]       = d0 * inv * g[t] + bb[t];
    hs[t + 256] = d1 * inv * g[t + 256] + bb[t + 256];
    __syncthreads();
    int o = blockIdx.y * 256 + t;
    if (o >= NCLS) return;
    float acc = bias[o];
    #pragma unroll 8
    for (int d = 0; d < DIMM; d++) acc += hs[d] * W[(size_t)d * NCLS + o];
    out[(size_t)b * NCLS + o] = acc;
}

// ---------------- launch ----------------
extern "C" void kernel_launch(void* const* d_in, const int* in_sizes, int n_in,
                              void* d_out, int out_size) {
    const float* img     = (const float*)d_in[0];
    const float* patch_w = (const float*)d_in[1];
    const float* patch_b = (const float*)d_in[2];
    const float* pos_emb = (const float*)d_in[3];
    const float* cls_tok = (const float*)d_in[4];
    const float* ln1_g   = (const float*)d_in[5];
    const float* ln1_b   = (const float*)d_in[6];
    const float* Wq      = (const float*)d_in[7];
    const float* Wk      = (const float*)d_in[8];
    const float* Wv      = (const float*)d_in[9];
    const float* Wg      = (const float*)d_in[10];
    const float* Wo      = (const float*)d_in[11];
    const float* kpe     = (const float*)d_in[12];
    const float* vpe     = (const float*)d_in[13];
    const float* Wkc     = (const float*)d_in[14];
    const float* Wvc     = (const float*)d_in[15];
    const float* ln2_g   = (const float*)d_in[16];
    const float* ln2_b   = (const float*)d_in[17];
    const float* ff_w1   = (const float*)d_in[18];
    const float* ff_b1   = (const float*)d_in[19];
    const float* ff_w2   = (const float*)d_in[20];
    const float* ff_b2   = (const float*)d_in[21];
    const float* hln_g   = (const float*)d_in[22];
    const float* hln_b   = (const float*)d_in[23];
    const float* head_w  = (const float*)d_in[24];
    const float* head_b  = (const float*)d_in[25];

    float *x, *h, *q, *k, *v, *gate, *ckcv, *outc, *attn, *mlp, *prt;
    int* selb;
    cudaGetSymbolAddress((void**)&x, g_x);
    cudaGetSymbolAddress((void**)&h, g_h);
    cudaGetSymbolAddress((void**)&q, g_q);
    cudaGetSymbolAddress((void**)&k, g_k);
    cudaGetSymbolAddress((void**)&v, g_v);
    cudaGetSymbolAddress((void**)&gate, g_gate);
    cudaGetSymbolAddress((void**)&ckcv, g_ckcv);
    cudaGetSymbolAddress((void**)&outc, g_outc);
    cudaGetSymbolAddress((void**)&selb, g_selb);
    cudaGetSymbolAddress((void**)&attn, g_attn);
    cudaGetSymbolAddress((void**)&mlp, g_mlp);
    cudaGetSymbolAddress((void**)&prt, g_part);

    const int CCN4 = (2 * CM * 64) / 4;
    const int CCRG = (CCN4 + 255) / 256;
    float* ck = ckcv;
    float* cv = ckcv + (size_t)CM * 64;

    patch_embed_ln_kernel<<<BB * NTOK, 256>>>(img, patch_w, patch_b, pos_emb,
                                              cls_tok, ln1_g, ln1_b, x, h);

    for (int l = 0; l < 2; l++) {
        const float* Wql = Wq + (size_t)l * DIMM * DIMM;
        const float* Wkl = Wk + (size_t)l * DIMM * DIMM;
        const float* Wvl = Wv + (size_t)l * DIMM * DIMM;
        const float* Wgl = Wg + (size_t)l * DIMM * 24;
        const float* Wol = Wo + (size_t)l * DIMM * DIMM;
        const float* kpel = kpe + (size_t)l * 16 * DHH;
        const float* vpel = vpe + (size_t)l * 16 * DHH;
        const float* Wkcl = Wkc + (size_t)l * 1024 * DHH;
        const float* Wvcl = Wvc + (size_t)l * 1024 * DHH;

        qkvgW_kernel<<<dim3(13, 19), 256>>>(h, Wql, Wkl, Wvl, Wgl, q, k, v, gate);

        compress_gemm_kernel<<<dim3((CM + 63) / 64, 2, 8), 256>>>(
            k, v, kpel, vpel, Wkcl, Wvcl, prt);
        reduce8_kernel<<<CCRG, 256>>>(prt, ckcv, CCN4);

        cattn_kernel<<<BB * HH * NQBA, 256>>>(q, ck, cv, outc, selb);
        swc_tile_kernel<<<BB * HH * NQT, 256>>>(q, k, v, outc, gate, selb, attn);

        gemmW_split_kernel<<<dim3(4, 19, 4), 256>>>(attn, Wol, prt, BN, DIMM, DIMM);
        reduce_ln_kernel<<<BN, 128>>>(prt, (const float*)0, x, x,
                                      ln2_g + l * DIMM, ln2_b + l * DIMM, h, 4);

        gemmW_kernel<<<dim3(16, 19), 256>>>(h, ff_w1 + (size_t)l * DIMM * MLPD,
                                            ff_b1 + (size_t)l * MLPD, (const float*)0,
                                            mlp, BN, MLPD, DIMM, ACT_GELU);

        gemmW_split_kernel<<<dim3(4, 19, 4), 256>>>(mlp, ff_w2 + (size_t)l * MLPD * DIMM,
                                                    prt, BN, DIMM, MLPD);
        if (l == 0) {
            reduce_ln_kernel<<<BN, 128>>>(prt, ff_b2, x, x,
                                          ln1_g + DIMM, ln1_b + DIMM, h, 4);
        } else {
            reduce_ln_kernel<<<BN, 128>>>(prt, ff_b2 + (size_t)l * DIMM, x, x,
                                          (const float*)0, (const float*)0, h, 4);
        }
    }

    head_ln_kernel<<<dim3(BB, (NCLS + 255) / 256), 256>>>(
        x, hln_g, hln_b, head_w, head_b, (float*)d_out);
}

// round 17
// speedup vs baseline: 1.1167x; 1.0023x over previous
#include <cuda_runtime.h>
#include <math.h>

// ---------------- problem constants ----------------
#define BB   2
#define NTOK 577
#define DIMM 512
#define HH   8
#define DHH  64
#define NCC  145
#define NSB  10
#define KSEL 4
#define SWIN 32
#define MLPD 2048
#define NCLS 1000
#define BN   (BB*NTOK)    // 1154
#define QCA  12
#define NQBA 49
#define CM   (BB*HH*NCC)  // 2320
#define QT   16
#define NQT  37
#define PARTSZ (16*CM*64)

#define ACT_NONE 0
#define ACT_GELU 1
#define ACT_SIG  2

// ---------------- device scratch ----------------
__device__ float g_x   [BN*DIMM];
__device__ float g_h   [BN*DIMM];
__device__ float g_q   [BN*DIMM];
__device__ float g_k   [BN*DIMM];
__device__ float g_v   [BN*DIMM];
__device__ float g_gate[BN*24];
__device__ float g_ckcv[2*CM*DHH];
__device__ float g_outc[BB*HH*NTOK*DHH];
__device__ int   g_selb[BB*HH*NTOK*KSEL];
__device__ float g_attn[BN*DIMM];
__device__ float g_mlp [BN*MLPD];
__device__ float g_part[PARTSZ];

// ---------------- helpers ----------------
__device__ __forceinline__ float gelu_tanh(float x) {
    float x3 = x * x * x;
    return 0.5f * x * (1.0f + tanhf(0.7978845608028654f * (x + 0.044715f * x3)));
}

__device__ __forceinline__ float blk_sum256(float v, float* sred) {
    #pragma unroll
    for (int o = 16; o; o >>= 1) v += __shfl_xor_sync(0xffffffffu, v, o);
    __syncthreads();
    if ((threadIdx.x & 31) == 0) sred[threadIdx.x >> 5] = v;
    __syncthreads();
    float r = sred[0];
    #pragma unroll
    for (int w = 1; w < 8; w++) r += sred[w];
    return r;
}
__device__ __forceinline__ float blk_sum128(float v, float* sred) {
    #pragma unroll
    for (int o = 16; o; o >>= 1) v += __shfl_xor_sync(0xffffffffu, v, o);
    __syncthreads();
    if ((threadIdx.x & 31) == 0) sred[threadIdx.x >> 5] = v;
    __syncthreads();
    return sred[0] + sred[1] + sred[2] + sred[3];
}

// ---------------- patch embed + cls + pos + fused LN1(layer0) ----------------
__global__ __launch_bounds__(256) void patch_embed_ln_kernel(
    const float* __restrict__ img, const float* __restrict__ pw,
    const float* __restrict__ pb, const float* __restrict__ pos,
    const float* __restrict__ cls,
    const float* __restrict__ g, const float* __restrict__ bb,
    float* __restrict__ x, float* __restrict__ h)
{
    __shared__ float sred[8];
    int t = blockIdx.x % NTOK;
    int b = blockIdx.x / NTOK;
    int tid = threadIdx.x;
    float val[2];
    #pragma unroll
    for (int half = 0; half < 2; half++) {
        int d = tid + half * 256;
        float v;
        if (t == 0) {
            v = cls[d];
        } else {
            int p = t - 1;
            int ii = p / 24, jj = p % 24;
            v = pb[d];
            #pragma unroll
            for (int c = 0; c < 3; c++)
                v += img[((b * 3 + c) * 24 + ii) * 24 + jj] * pw[c * DIMM + d];
        }
        val[half] = v + pos[(size_t)t * DIMM + d];
    }
    size_t off = (size_t)(b * NTOK + t) * DIMM;
    x[off + tid]       = val[0];
    x[off + tid + 256] = val[1];
    float mean = blk_sum256(val[0] + val[1], sred) * (1.0f / 512.0f);
    float d0 = val[0] - mean, d1 = val[1] - mean;
    __syncthreads();
    float var = blk_sum256(d0 * d0 + d1 * d1, sred) * (1.0f / 512.0f);
    float inv = rsqrtf(var + 1e-5f);
    h[off + tid]       = d0 * inv * g[tid] + bb[tid];
    h[off + tid + 256] = d1 * inv * g[tid + 256] + bb[tid + 256];
}

// ---------------- SGEMM core A: 64x64 tile, 4x4/thread ----------------
__device__ __forceinline__ void gemm_core(
    const float* __restrict__ A, const float* __restrict__ W,
    const float* __restrict__ bias, const float* __restrict__ res,
    float* __restrict__ C, float* __restrict__ part,
    int M, int Nn, int K, int act, int row0, int col0, int k0, int kLen)
{
    __shared__ __align__(16) float As[2][16][68];
    __shared__ __align__(16) float Bs[2][16][64];
    int tid = threadIdx.x;
    int tx = tid & 15, ty = tid >> 4;

    int am  = tid >> 2;
    int akq = tid & 3;
    int arow = row0 + am;
    const float* Aptr = (arow < M) ? (A + (size_t)arow * K + k0 + akq * 4) : (const float*)0;
    int bkk = tid >> 4;
    int bnq = tid & 15;
    int bcol = col0 + bnq * 4;
    const float* Wptr = W + (size_t)(k0 + bkk) * Nn + bcol;
    bool bfull = (bcol + 3 < Nn);
    bool bany  = (bcol < Nn);

    float4 a4, b4;
    if (Aptr) a4 = *(const float4*)(Aptr);
    else      a4 = make_float4(0.f, 0.f, 0.f, 0.f);
    if (bfull) b4 = *(const float4*)(Wptr);
    else {
        b4 = make_float4(0.f, 0.f, 0.f, 0.f);
        if (bany) {
            b4.x = Wptr[0];
            if (bcol + 1 < Nn) b4.y = Wptr[1];
            if (bcol + 2 < Nn) b4.z = Wptr[2];
        }
    }
    As[0][akq * 4 + 0][am] = a4.x;
    As[0][akq * 4 + 1][am] = a4.y;
    As[0][akq * 4 + 2][am] = a4.z;
    As[0][akq * 4 + 3][am] = a4.w;
    *(float4*)&Bs[0][bkk][bnq * 4] = b4;
    __syncthreads();

    float acc[4][4];
    #pragma unroll
    for (int i = 0; i < 4; i++)
        #pragma unroll
        for (int j = 0; j < 4; j++) acc[i][j] = 0.f;

    int steps = kLen >> 4;
    for (int ks = 0; ks < steps; ks++) {
        int cur = ks & 1;
        bool hn = (ks + 1 < steps);
        if (hn) {
            int kk0 = (ks + 1) * 16;
            if (Aptr) a4 = *(const float4*)(Aptr + kk0);
            else      a4 = make_float4(0.f, 0.f, 0.f, 0.f);
            if (bfull) b4 = *(const float4*)(Wptr + (size_t)kk0 * Nn);
            else {
                b4 = make_float4(0.f, 0.f, 0.f, 0.f);
                if (bany) {
                    const float* p = Wptr + (size_t)kk0 * Nn;
                    b4.x = p[0];
                    if (bcol + 1 < Nn) b4.y = p[1];
                    if (bcol + 2 < Nn) b4.z = p[2];
                }
            }
        }
        #pragma unroll
        for (int kk = 0; kk < 16; kk++) {
            float4 av = *(const float4*)&As[cur][kk][ty * 4];
            float4 bv = *(const float4*)&Bs[cur][kk][tx * 4];
            acc[0][0] += av.x * bv.x; acc[0][1] += av.x * bv.y; acc[0][2] += av.x * bv.z; acc[0][3] += av.x * bv.w;
            acc[1][0] += av.y * bv.x; acc[1][1] += av.y * bv.y; acc[1][2] += av.y * bv.z; acc[1][3] += av.y * bv.w;
            acc[2][0] += av.z * bv.x; acc[2][1] += av.z * bv.y; acc[2][2] += av.z * bv.z; acc[2][3] += av.z * bv.w;
            acc[3][0] += av.w * bv.x; acc[3][1] += av.w * bv.y; acc[3][2] += av.w * bv.z; acc[3][3] += av.w * bv.w;
        }
        if (hn) {
            int nxt = cur ^ 1;
            As[nxt][akq * 4 + 0][am] = a4.x;
            As[nxt][akq * 4 + 1][am] = a4.y;
            As[nxt][akq * 4 + 2][am] = a4.z;
            As[nxt][akq * 4 + 3][am] = a4.w;
            *(float4*)&Bs[nxt][bkk][bnq * 4] = b4;
            __syncthreads();
        }
    }
    #pragma unroll
    for (int i = 0; i < 4; i++) {
        int r = row0 + ty * 4 + i;
        if (r >= M) continue;
        #pragma unroll
        for (int j = 0; j < 4; j++) {
            int c = col0 + tx * 4 + j;
            if (c >= Nn) continue;
            float v = acc[i][j];
            size_t off = (size_t)r * Nn + c;
            if (part) {
                part[off] = v;
            } else {
                if (bias) v += bias[c];
                if (act == ACT_GELU) v = gelu_tanh(v);
                else if (act == ACT_SIG) v = 1.0f / (1.0f + expf(-v));
                if (res) v += res[off];
                C[off] = v;
            }
        }
    }
}

// ---------------- SGEMM core B: 64x128 tile, 4x8/thread ----------------
__device__ __forceinline__ void gemmW_core(
    const float* __restrict__ A, const float* __restrict__ W,
    const float* __restrict__ bias, const float* __restrict__ res,
    float* __restrict__ C, float* __restrict__ part,
    int M, int Nn, int K, int act, int row0, int col0, int k0, int kLen)
{
    __shared__ __align__(16) float As[2][16][68];
    __shared__ __align__(16) float Bs[2][16][128];
    int tid = threadIdx.x;
    int tx = tid & 15, ty = tid >> 4;

    int am  = tid >> 2;
    int akq = tid & 3;
    int arow = row0 + am;
    const float* Aptr = (arow < M) ? (A + (size_t)arow * K + k0 + akq * 4) : (const float*)0;
    int bkk = tid >> 4;
    int bnq = tid & 15;
    const float* Wptr = W + (size_t)(k0 + bkk) * Nn + col0 + bnq * 4;

    float4 a4, b4a, b4b;
    if (Aptr) a4 = *(const float4*)(Aptr);
    else      a4 = make_float4(0.f, 0.f, 0.f, 0.f);
    b4a = *(const float4*)(Wptr);
    b4b = *(const float4*)(Wptr + 64);
    As[0][akq * 4 + 0][am] = a4.x;
    As[0][akq * 4 + 1][am] = a4.y;
    As[0][akq * 4 + 2][am] = a4.z;
    As[0][akq * 4 + 3][am] = a4.w;
    *(float4*)&Bs[0][bkk][bnq * 4]      = b4a;
    *(float4*)&Bs[0][bkk][64 + bnq * 4] = b4b;
    __syncthreads();

    float acc[4][8];
    #pragma unroll
    for (int i = 0; i < 4; i++)
        #pragma unroll
        for (int j = 0; j < 8; j++) acc[i][j] = 0.f;

    int steps = kLen >> 4;
    for (int ks = 0; ks < steps; ks++) {
        int cur = ks & 1;
        bool hn = (ks + 1 < steps);
        if (hn) {
            int kk0 = (ks + 1) * 16;
            if (Aptr) a4 = *(const float4*)(Aptr + kk0);
            else      a4 = make_float4(0.f, 0.f, 0.f, 0.f);
            const float* p = Wptr + (size_t)kk0 * Nn;
            b4a = *(const float4*)(p);
            b4b = *(const float4*)(p + 64);
        }
        #pragma unroll
        for (int kk = 0; kk < 16; kk++) {
            float4 av = *(const float4*)&As[cur][kk][ty * 4];
            float4 bv0 = *(const float4*)&Bs[cur][kk][tx * 4];
            float4 bv1 = *(const float4*)&Bs[cur][kk][64 + tx * 4];
            float a0 = av.x, a1 = av.y, a2 = av.z, a3 = av.w;
            acc[0][0] += a0 * bv0.x; acc[0][1] += a0 * bv0.y; acc[0][2] += a0 * bv0.z; acc[0][3] += a0 * bv0.w;
            acc[0][4] += a0 * bv1.x; acc[0][5] += a0 * bv1.y; acc[0][6] += a0 * bv1.z; acc[0][7] += a0 * bv1.w;
            acc[1][0] += a1 * bv0.x; acc[1][1] += a1 * bv0.y; acc[1][2] += a1 * bv0.z; acc[1][3] += a1 * bv0.w;
            acc[1][4] += a1 * bv1.x; acc[1][5] += a1 * bv1.y; acc[1][6] += a1 * bv1.z; acc[1][7] += a1 * bv1.w;
            acc[2][0] += a2 * bv0.x; acc[2][1] += a2 * bv0.y; acc[2][2] += a2 * bv0.z; acc[2][3] += a2 * bv0.w;
            acc[2][4] += a2 * bv1.x; acc[2][5] += a2 * bv1.y; acc[2][6] += a2 * bv1.z; acc[2][7] += a2 * bv1.w;
            acc[3][0] += a3 * bv0.x; acc[3][1] += a3 * bv0.y; acc[3][2] += a3 * bv0.z; acc[3][3] += a3 * bv0.w;
            acc[3][4] += a3 * bv1.x; acc[3][5] += a3 * bv1.y; acc[3][6] += a3 * bv1.z; acc[3][7] += a3 * bv1.w;
        }
        if (hn) {
            int nxt = cur ^ 1;
            As[nxt][akq * 4 + 0][am] = a4.x;
            As[nxt][akq * 4 + 1][am] = a4.y;
            As[nxt][akq * 4 + 2][am] = a4.z;
            As[nxt][akq * 4 + 3][am] = a4.w;
            *(float4*)&Bs[nxt][bkk][bnq * 4]      = b4a;
            *(float4*)&Bs[nxt][bkk][64 + bnq * 4] = b4b;
            __syncthreads();
        }
    }
    #pragma unroll
    for (int i = 0; i < 4; i++) {
        int r = row0 + ty * 4 + i;
        if (r >= M) continue;
        #pragma unroll
        for (int half = 0; half < 2; half++) {
            int c = col0 + half * 64 + tx * 4;
            size_t off = (size_t)r * Nn + c;
            float4 v;
            v.x = acc[i][half * 4 + 0]; v.y = acc[i][half * 4 + 1];
            v.z = acc[i][half * 4 + 2]; v.w = acc[i][half * 4 + 3];
            if (part) {
                *(float4*)(part + off) = v;
            } else {
                if (bias) {
                    v.x += bias[c]; v.y += bias[c + 1];
                    v.z += bias[c + 2]; v.w += bias[c + 3];
                }
                if (act == ACT_GELU) {
                    v.x = gelu_tanh(v.x); v.y = gelu_tanh(v.y);
                    v.z = gelu_tanh(v.z); v.w = gelu_tanh(v.w);
                }
                if (res) {
                    float4 r4 = *(const float4*)(res + off);
                    v.x += r4.x; v.y += r4.y; v.z += r4.z; v.w += r4.w;
                }
                *(float4*)(C + off) = v;
            }
        }
    }
}

__global__ __launch_bounds__(256) void gemmW_kernel(
    const float* __restrict__ A, const float* __restrict__ W,
    const float* __restrict__ bias, const float* __restrict__ res,
    float* __restrict__ C, int M, int Nn, int K, int act)
{
    gemmW_core(A, W, bias, res, C, (float*)0, M, Nn, K, act,
               blockIdx.y * 64, blockIdx.x * 128, 0, K);
}

__global__ __launch_bounds__(256) void gemmW_split_kernel(
    const float* __restrict__ A, const float* __restrict__ W,
    float* __restrict__ part, int M, int Nn, int K)
{
    int chunk = K / gridDim.z;
    float* p = part + (size_t)blockIdx.z * M * Nn;
    gemmW_core(A, W, (const float*)0, (const float*)0, (float*)0, p,
               M, Nn, K, ACT_NONE,
               blockIdx.y * 64, blockIdx.x * 128, blockIdx.z * chunk, chunk);
}

// fused QKV (64x128 core) + gate (64x64 core)
__global__ __launch_bounds__(256) void qkvgW_kernel(
    const float* __restrict__ h,
    const float* __restrict__ Wq, const float* __restrict__ Wk,
    const float* __restrict__ Wv, const float* __restrict__ Wg,
    float* __restrict__ q, float* __restrict__ k,
    float* __restrict__ v, float* __restrict__ gate)
{
    int bx = blockIdx.x;
    if (bx < 12) {
        int sel = bx >> 2;
        const float* W; float* C;
        if (sel == 0)      { W = Wq; C = q; }
        else if (sel == 1) { W = Wk; C = k; }
        else               { W = Wv; C = v; }
        gemmW_core(h, W, (const float*)0, (const float*)0, C, (float*)0,
                   BN, DIMM, DIMM, ACT_NONE, blockIdx.y * 64, (bx & 3) * 128, 0, DIMM);
    } else {
        gemm_core(h, Wg, (const float*)0, (const float*)0, gate, (float*)0,
                  BN, 24, DIMM, ACT_SIG, blockIdx.y * 64, 0, 0, DIMM);
    }
}

// ---------------- fused split-K reduce + residual + LayerNorm ----------------
__global__ __launch_bounds__(128) void reduce_ln_kernel(
    const float* __restrict__ part, const float* __restrict__ bias,
    const float* __restrict__ res, float* __restrict__ x,
    const float* __restrict__ gamma, const float* __restrict__ beta,
    float* __restrict__ h, int S)
{
    __shared__ float sred[4];
    int r = blockIdx.x;
    int t = threadIdx.x;
    int c = t * 4;
    size_t off = (size_t)r * DIMM + c;
    size_t stride = (size_t)BN * DIMM;
    float4 s = *(const float4*)(part + off);
    for (int i = 1; i < S; i++) {
        float4 p = *(const float4*)(part + (size_t)i * stride + off);
        s.x += p.x; s.y += p.y; s.z += p.z; s.w += p.w;
    }
    if (bias) {
        s.x += bias[c]; s.y += bias[c + 1]; s.z += bias[c + 2]; s.w += bias[c + 3];
    }
    if (res) {
        float4 r4 = *(const float4*)(res + off);
        s.x += r4.x; s.y += r4.y; s.z += r4.z; s.w += r4.w;
    }
    *(float4*)(x + off) = s;
    if (!gamma) return;
    float mean = blk_sum128(s.x + s.y + s.z + s.w, sred) * (1.0f / 512.0f);
    float d0 = s.x - mean, d1 = s.y - mean, d2 = s.z - mean, d3 = s.w - mean;
    __syncthreads();
    float var = blk_sum128(d0 * d0 + d1 * d1 + d2 * d2 + d3 * d3, sred) * (1.0f / 512.0f);
    float inv = rsqrtf(var + 1e-5f);
    float4 o;
    o.x = d0 * inv * gamma[c]     + beta[c];
    o.y = d1 * inv * gamma[c + 1] + beta[c + 1];
    o.z = d2 * inv * gamma[c + 2] + beta[c + 2];
    o.w = d3 * inv * gamma[c + 3] + beta[c + 3];
    *(float4*)(h + off) = o;
}

// specialized S=8 split-K reduce (compress path): 8 independent loads, tree sum
__global__ __launch_bounds__(128) void reduce8_kernel(
    const float* __restrict__ part, float* __restrict__ C, int MN4)
{
    int idx = blockIdx.x * 128 + threadIdx.x;
    if (idx >= MN4) return;
    size_t off = (size_t)idx * 4;
    size_t stride = (size_t)MN4 * 4;
    float4 p0 = *(const float4*)(part + off);
    float4 p1 = *(const float4*)(part + stride + off);
    float4 p2 = *(const float4*)(part + 2 * stride + off);
    float4 p3 = *(const float4*)(part + 3 * stride + off);
    float4 p4 = *(const float4*)(part + 4 * stride + off);
    float4 p5 = *(const float4*)(part + 5 * stride + off);
    float4 p6 = *(const float4*)(part + 6 * stride + off);
    float4 p7 = *(const float4*)(part + 7 * stride + off);
    float4 s;
    s.x = ((p0.x + p1.x) + (p2.x + p3.x)) + ((p4.x + p5.x) + (p6.x + p7.x));
    s.y = ((p0.y + p1.y) + (p2.y + p3.y)) + ((p4.y + p5.y) + (p6.y + p7.y));
    s.z = ((p0.z + p1.z) + (p2.z + p3.z)) + ((p4.z + p5.z) + (p6.z + p7.z));
    s.w = ((p0.w + p1.w) + (p2.w + p3.w)) + ((p4.w + p5.w) + (p6.w + p7.w));
    *(float4*)(C + off) = s;
}

// ---------------- compress as gather-A GEMM, split-K x8 ----------------
__global__ __launch_bounds__(256) void compress_gemm_kernel(
    const float* __restrict__ kin, const float* __restrict__ vin,
    const float* __restrict__ kpe, const float* __restrict__ vpe,
    const float* __restrict__ Wkc, const float* __restrict__ Wvc,
    float* __restrict__ part)
{
    const float* in; const float* pe; const float* Wc;
    if (blockIdx.y == 0) { in = kin; pe = kpe; Wc = Wkc; }
    else                 { in = vin; pe = vpe; Wc = Wvc; }
    float* out = part + ((size_t)(blockIdx.z * 2 + blockIdx.y)) * CM * 64;
    int k0 = blockIdx.z * 128;

    __shared__ __align__(16) float As[2][16][68];
    __shared__ __align__(16) float Bs[2][16][64];
    int tid = threadIdx.x;
    int tx = tid & 15, ty = tid >> 4;
    int row0 = blockIdx.x * 64;

    int am  = tid >> 2;
    int akq = tid & 3;
    int row = row0 + am;
    bool avalid = row < CM;
    int rr = avalid ? row : CM - 1;
    int bh = rr / NCC, j = rr - bh * NCC;
    int b = bh >> 3, hh = bh & 7;
    const float* kb = in + (size_t)b * NTOK * DIMM + hh * DHH;
    int j4 = j * 4;

    auto fetchA = [&](int e) -> float4 {
        float4 p = *(const float4*)(pe + e);
        int jj = e >> 6, d = e & 63;
        int tok = j4 + jj;
        if (tok < NTOK) {
            float4 kv = *(const float4*)(kb + (size_t)tok * DIMM + d);
            p.x += kv.x; p.y += kv.y; p.z += kv.z; p.w += kv.w;
        }
        return p;
    };

    int bkk = tid >> 4;
    int bnq = tid & 15;
    const float* Wptr = Wc + (size_t)(k0 + bkk) * 64 + bnq * 4;

    float4 a4 = avalid ? fetchA(k0 + akq * 4) : make_float4(0.f, 0.f, 0.f, 0.f);
    float4 b4 = *(const float4*)(Wptr);
    As[0][akq * 4 + 0][am] = a4.x;
    As[0][akq * 4 + 1][am] = a4.y;
    As[0][akq * 4 + 2][am] = a4.z;
    As[0][akq * 4 + 3][am] = a4.w;
    *(float4*)&Bs[0][bkk][bnq * 4] = b4;
    __syncthreads();

    float acc[4][4];
    #pragma unroll
    for (int i = 0; i < 4; i++)
        #pragma unroll
        for (int jq = 0; jq < 4; jq++) acc[i][jq] = 0.f;

    const int steps = 8;
    for (int ks = 0; ks < steps; ks++) {
        int cur = ks & 1;
        bool hn = (ks + 1 < steps);
        if (hn) {
            int e = k0 + (ks + 1) * 16 + akq * 4;
            a4 = avalid ? fetchA(e) : make_float4(0.f, 0.f, 0.f, 0.f);
            b4 = *(const float4*)(Wptr + (size_t)(ks + 1) * 16 * 64);
        }
        #pragma unroll
        for (int kk = 0; kk < 16; kk++) {
            float4 av = *(const float4*)&As[cur][kk][ty * 4];
            float4 bv = *(const float4*)&Bs[cur][kk][tx * 4];
            acc[0][0] += av.x * bv.x; acc[0][1] += av.x * bv.y; acc[0][2] += av.x * bv.z; acc[0][3] += av.x * bv.w;
            acc[1][0] += av.y * bv.x; acc[1][1] += av.y * bv.y; acc[1][2] += av.y * bv.z; acc[1][3] += av.y * bv.w;
            acc[2][0] += av.z * bv.x; acc[2][1] += av.z * bv.y; acc[2][2] += av.z * bv.z; acc[2][3] += av.z * bv.w;
            acc[3][0] += av.w * bv.x; acc[3][1] += av.w * bv.y; acc[3][2] += av.w * bv.z; acc[3][3] += av.w * bv.w;
        }
        if (hn) {
            int nxt = cur ^ 1;
            As[nxt][akq * 4 + 0][am] = a4.x;
            As[nxt][akq * 4 + 1][am] = a4.y;
            As[nxt][akq * 4 + 2][am] = a4.z;
            As[nxt][akq * 4 + 3][am] = a4.w;
            *(float4*)&Bs[nxt][bkk][bnq * 4] = b4;
            __syncthreads();
        }
    }
    #pragma unroll
    for (int i = 0; i < 4; i++) {
        int r = row0 + ty * 4 + i;
        if (r >= CM) continue;
        int c = tx * 4;
        *(float4*)(out + (size_t)r * 64 + c) =
            make_float4(acc[i][0], acc[i][1], acc[i][2], acc[i][3]);
    }
}

// ---------------- compressed attention + top-k (12 queries/block) ----------------
__global__ __launch_bounds__(256) void cattn_kernel(
    const float* __restrict__ q, const float* __restrict__ ck,
    const float* __restrict__ cv, float* __restrict__ outc,
    int* __restrict__ selb)
{
    __shared__ float cbuf[NCC * 65];
    __shared__ float qs[QCA * 64];
    __shared__ float sc[QCA][NCC];
    int blk = blockIdx.x;
    int qb = blk % NQBA, bh = blk / NQBA;
    int h = bh % HH, b = bh / HH;
    int i0 = qb * QCA;
    int tid = threadIdx.x;
    for (int idx = tid; idx < QCA * 64; idx += 256) {
        int u = idx >> 6, d2 = idx & 63, i = i0 + u;
        qs[idx] = (i < NTOK) ? q[((size_t)(b * NTOK + i)) * DIMM + h * DHH + d2] : 0.f;
    }
    const float* ckb = ck + (size_t)bh * NCC * DHH;
    for (int idx = tid; idx < NCC * 64; idx += 256) {
        int j = idx >> 6, d2 = idx & 63;
        cbuf[j * 65 + d2] = ckb[idx];
    }
    __syncthreads();
    for (int p = tid; p < QCA * NCC; p += 256) {
        int u = p / NCC, j = p % NCC;
        const float* cr = &cbuf[j * 65];
        const float* qr = &qs[u * 64];
        float a = 0.f;
        #pragma unroll
        for (int d2 = 0; d2 < 64; d2++) a += qr[d2] * cr[d2];
        sc[u][j] = a * 0.125f;
    }
    __syncthreads();
    // prestage cv into cbuf NOW: its load latency hides behind softmax + top-k
    const float* cvb = cv + (size_t)bh * NCC * DHH;
    for (int idx = tid; idx < NCC * 64; idx += 256) {
        int j = idx >> 6, d2 = idx & 63;
        cbuf[j * 65 + d2] = cvb[idx];
    }
    int w = tid >> 5, ln = tid & 31;
    for (int u = w; u < QCA; u += 8) {
        float m = -1e30f;
        for (int j = ln; j < NCC; j += 32) m = fmaxf(m, sc[u][j]);
        #pragma unroll
        for (int o = 16; o; o >>= 1) m = fmaxf(m, __shfl_xor_sync(0xffffffffu, m, o));
        float s = 0.f;
        for (int j = ln; j < NCC; j += 32) { float e = expf(sc[u][j] - m); sc[u][j] = e; s += e; }
        #pragma unroll
        for (int o = 16; o; o >>= 1) s += __shfl_xor_sync(0xffffffffu, s, o);
        float inv = 1.f / s;
        for (int j = ln; j < NCC; j += 32) sc[u][j] *= inv;
    }
    __syncthreads();
    if (tid < QCA) {
        int i = i0 + tid;
        if (i < NTOK) {
            float imp[NSB];
            #pragma unroll
            for (int t = 0; t < NSB; t++) imp[t] = 0.f;
            for (int j = 0; j < NCC; j++) {
                int c = (j + 2) >> 4; if (c > NSB - 1) c = NSB - 1;
                imp[c] += sc[tid][j];
            }
            size_t gi = (size_t)bh * NTOK + i;
            #pragma unroll
            for (int t = 0; t < KSEL; t++) {
                float best = -1e30f; int bi = 0;
                #pragma unroll
                for (int sbv = 0; sbv < NSB; sbv++)
                    if (imp[sbv] > best) { best = imp[sbv]; bi = sbv; }
                selb[gi * KSEL + t] = bi;
                imp[bi] = -2e30f;
            }
        }
    }
    __syncthreads();
    // PV: register-blocked over 3 queries per thread group
    {
        int grp = tid >> 6, d2 = tid & 63;
        int u0 = grp * 3;
        float a0 = 0.f, a1 = 0.f, a2 = 0.f;
        for (int j = 0; j < NCC; j++) {
            float cvv = cbuf[j * 65 + d2];
            a0 += sc[u0][j] * cvv;
            a1 += sc[u0 + 1][j] * cvv;
            a2 += sc[u0 + 2][j] * cvv;
        }
        float av[3] = {a0, a1, a2};
        #pragma unroll
        for (int e = 0; e < 3; e++) {
            int i = i0 + u0 + e;
            if (i < NTOK)
                outc[((size_t)(bh * NTOK + i)) * 64 + d2] = av[e];
        }
    }
}

// ==== tiled: selected-block attn + sliding window + gate combine (16 q/block) ====
__global__ __launch_bounds__(256) void swc_tile_kernel(
    const float* __restrict__ q, const float* __restrict__ k,
    const float* __restrict__ v, const float* __restrict__ outc,
    const float* __restrict__ gate, const int* __restrict__ selb,
    float* __restrict__ attn)
{
    __shared__ float qs[QT * 64];
    __shared__ float kvb[64 * 65];
    __shared__ float ss[QT][256];
    __shared__ float pw[QT][33];
    __shared__ int   sb[QT][4];
    __shared__ unsigned smask;

    int bx = blockIdx.x;
    int qt = bx % NQT;
    int bh = bx / NQT;
    int hd = bh % HH, b = bh / HH;
    int i0 = qt * QT;
    int tid = threadIdx.x;
    int lane = tid & 31, w = tid >> 5;

    for (int idx = tid; idx < QT * 64; idx += 256) {
        int u = idx >> 6, d = idx & 63;
        int i = i0 + u;
        qs[idx] = (i < NTOK) ? q[((size_t)(b * NTOK + i)) * DIMM + hd * DHH + d] : 0.f;
    }
    if (tid == 0) smask = 0;
    if (tid < QT * 4) {
        int u = tid >> 2, c = tid & 3;
        int i = i0 + u;
        sb[u][c] = (i < NTOK) ? selb[((size_t)(bh * NTOK + i)) * KSEL + c] : -1;
    }
    __syncthreads();
    if (tid < QT * 4) {
        int s = sb[tid >> 2][tid & 3];
        if (s >= 0) atomicOr(&smask, 1u << s);
    }
    __syncthreads();
    unsigned mask = smask;

    const float* kbase = k + (size_t)b * NTOK * DIMM + hd * DHH;
    const float* vbase = v + (size_t)b * NTOK * DIMM + hd * DHH;

    for (int sblk = 0; sblk < NSB; sblk++) {
        if (!((mask >> sblk) & 1u)) continue;
        for (int idx = tid; idx < 4096; idx += 256) {
            int t = idx >> 6, d = idx & 63;
            int tok = sblk * 64 + t; int tk = tok < NTOK ? tok : NTOK - 1;
            kvb[t * 65 + d] = kbase[(size_t)tk * DIMM + d];
        }
        __syncthreads();
        #pragma unroll
        for (int uu = 0; uu < 2; uu++) {
            int u = w * 2 + uu;
            #pragma unroll
            for (int c = 0; c < 4; c++) {
                if (sb[u][c] != sblk) continue;
                const float* qr = &qs[u * 64];
                #pragma unroll
                for (int tt = 0; tt < 2; tt++) {
                    int t = lane + tt * 32;
                    const float* kr = &kvb[t * 65];
                    float a = 0.f;
                    #pragma unroll
                    for (int d = 0; d < 64; d++) a += qr[d] * kr[d];
                    int tok = sblk * 64 + t;
                    ss[u][c * 64 + t] = (tok < NTOK) ? a * 0.125f : -1e30f;
                }
            }
        }
        __syncthreads();
    }

    #pragma unroll
    for (int uu = 0; uu < 2; uu++) {
        int u = w * 2 + uu;
        if (i0 + u < NTOK) {
            float m = -1e30f;
            #pragma unroll
            for (int j = 0; j < 8; j++) m = fmaxf(m, ss[u][lane + j * 32]);
            #pragma unroll
            for (int o = 16; o; o >>= 1) m = fmaxf(m, __shfl_xor_sync(0xffffffffu, m, o));
            float s = 0.f;
            #pragma unroll
            for (int j = 0; j < 8; j++) {
                float e = expf(ss[u][lane + j * 32] - m);
                ss[u][lane + j * 32] = e; s += e;
            }
            #pragma unroll
            for (int o = 16; o; o >>= 1) s += __shfl_xor_sync(0xffffffffu, s, o);
            float inv = 1.f / s;
            #pragma unroll
            for (int j = 0; j < 8; j++) ss[u][lane + j * 32] *= inv;
        }
    }
    __syncthreads();

    float accs[2][2] = {{0.f, 0.f}, {0.f, 0.f}};
    for (int sblk = 0; sblk < NSB; sblk++) {
        if (!((mask >> sblk) & 1u)) continue;
        for (int idx = tid; idx < 4096; idx += 256) {
            int t = idx >> 6, d = idx & 63;
            int tok = sblk * 64 + t; int tk = tok < NTOK ? tok : NTOK - 1;
            kvb[t * 65 + d] = vbase[(size_t)tk * DIMM + d];
        }
        __syncthreads();
        #pragma unroll
        for (int uu = 0; uu < 2; uu++) {
            int u = w * 2 + uu;
            #pragma unroll
            for (int c = 0; c < 4; c++) {
                if (sb[u][c] != sblk) continue;
                const float* pr = &ss[u][c * 64];
                for (int t = 0; t < 64; t++) {
                    float p = pr[t];
                    accs[uu][0] += p * kvb[t * 65 + lane];
                    accs[uu][1] += p * kvb[t * 65 + lane + 32];
                }
            }
        }
        __syncthreads();
    }

    const int WROWS = QT + SWIN - 1;
    int base = i0 - SWIN / 2;
    for (int idx = tid; idx < WROWS * 64; idx += 256) {
        int r = idx >> 6, d = idx & 63;
        int pos = base + r; int p = pos < 0 ? 0 : (pos > NTOK - 1 ? NTOK - 1 : pos);
        kvb[r * 65 + d] = kbase[(size_t)p * DIMM + d];
    }
    __syncthreads();
    #pragma unroll
    for (int uu = 0; uu < 2; uu++) {
        int u = w * 2 + uu;
        int i = i0 + u;
        int pos = i + lane - SWIN / 2;
        bool valid = (i < NTOK) && pos >= 0 && pos < NTOK;
        int r = u + lane;
        const float* qr = &qs[u * 64];
        const float* kr = &kvb[r * 65];
        float a = 0.f;
        #pragma unroll
        for (int d = 0; d < 64; d++) a += qr[d] * kr[d];
        float s = valid ? a * 0.125f : -1e30f;
        float m = s;
        #pragma unroll
        for (int o = 16; o; o >>= 1) m = fmaxf(m, __shfl_xor_sync(0xffffffffu, m, o));
        float e = expf(s - m);
        float t = e;
        #pragma unroll
        for (int o = 16; o; o >>= 1) t += __shfl_xor_sync(0xffffffffu, t, o);
        pw[u][lane] = e / t;
    }
    __syncthreads();
    for (int idx = tid; idx < WROWS * 64; idx += 256) {
        int r = idx >> 6, d = idx & 63;
        int pos = base + r; int p = pos < 0 ? 0 : (pos > NTOK - 1 ? NTOK - 1 : pos);
        kvb[r * 65 + d] = vbase[(size_t)p * DIMM + d];
    }
    __syncthreads();
    float accw[2][2] = {{0.f, 0.f}, {0.f, 0.f}};
    #pragma unroll
    for (int uu = 0; uu < 2; uu++) {
        int u = w * 2 + uu;
        for (int ww = 0; ww < SWIN; ww++) {
            float p = pw[u][ww];
            accw[uu][0] += p * kvb[(u + ww) * 65 + lane];
            accw[uu][1] += p * kvb[(u + ww) * 65 + lane + 32];
        }
    }

    #pragma unroll
    for (int uu = 0; uu < 2; uu++) {
        int u = w * 2 + uu;
        int i = i0 + u;
        if (i >= NTOK) continue;
        int row = b * NTOK + i;
        const float* gp = gate + (size_t)row * 24 + hd * 3;
        float g0 = gp[0], g1 = gp[1], g2 = gp[2];
        size_t gi = (size_t)bh * NTOK + i;
        #pragma unroll
        for (int dd = 0; dd < 2; dd++) {
            int d = lane + dd * 32;
            attn[(size_t)row * DIMM + hd * DHH + d] =
                g0 * outc[gi * 64 + d] + g1 * accs[uu][dd] + g2 * accw[uu][dd];
        }
    }
}

// ---------------- fused final LN + classifier head ----------------
__global__ __launch_bounds__(256) void head_ln_kernel(
    const float* __restrict__ x, const float* __restrict__ g,
    const float* __restrict__ bb, const float* __restrict__ W,
    const float* __restrict__ bias, float* __restrict__ out)
{
    __shared__ float sred[8];
    __shared__ float hs[DIMM];
    int b = blockIdx.x;
    int t = threadIdx.x;
    const float* row = x + (size_t)b * NTOK * DIMM;
    float a0 = row[t], a1 = row[t + 256];
    float mean = blk_sum256(a0 + a1, sred) * (1.0f / 512.0f);
    float d0 = a0 - mean, d1 = a1 - mean;
    __syncthreads();
    float var = blk_sum256(d0 * d0 + d1 * d1, sred) * (1.0f / 512.0f);
    float inv = rsqrtf(var + 1e-5f);
    hs[t]       = d0 * inv * g[t] + bb[t];
    hs[t + 256] = d1 * inv * g[t + 256] + bb[t + 256];
    __syncthreads();
    int o = blockIdx.y * 256 + t;
    if (o >= NCLS) return;
    float acc = bias[o];
    #pragma unroll 8
    for (int d = 0; d < DIMM; d++) acc += hs[d] * W[(size_t)d * NCLS + o];
    out[(size_t)b * NCLS + o] = acc;
}

// ---------------- launch ----------------
extern "C" void kernel_launch(void* const* d_in, const int* in_sizes, int n_in,
                              void* d_out, int out_size) {
    const float* img     = (const float*)d_in[0];
    const float* patch_w = (const float*)d_in[1];
    const float* patch_b = (const float*)d_in[2];
    const float* pos_emb = (const float*)d_in[3];
    const float* cls_tok = (const float*)d_in[4];
    const float* ln1_g   = (const float*)d_in[5];
    const float* ln1_b   = (const float*)d_in[6];
    const float* Wq      = (const float*)d_in[7];
    const float* Wk      = (const float*)d_in[8];
    const float* Wv      = (const float*)d_in[9];
    const float* Wg      = (const float*)d_in[10];
    const float* Wo      = (const float*)d_in[11];
    const float* kpe     = (const float*)d_in[12];
    const float* vpe     = (const float*)d_in[13];
    const float* Wkc     = (const float*)d_in[14];
    const float* Wvc     = (const float*)d_in[15];
    const float* ln2_g   = (const float*)d_in[16];
    const float* ln2_b   = (const float*)d_in[17];
    const float* ff_w1   = (const float*)d_in[18];
    const float* ff_b1   = (const float*)d_in[19];
    const float* ff_w2   = (const float*)d_in[20];
    const float* ff_b2   = (const float*)d_in[21];
    const float* hln_g   = (const float*)d_in[22];
    const float* hln_b   = (const float*)d_in[23];
    const float* head_w  = (const float*)d_in[24];
    const float* head_b  = (const float*)d_in[25];

    float *x, *h, *q, *k, *v, *gate, *ckcv, *outc, *attn, *mlp, *prt;
    int* selb;
    cudaGetSymbolAddress((void**)&x, g_x);
    cudaGetSymbolAddress((void**)&h, g_h);
    cudaGetSymbolAddress((void**)&q, g_q);
    cudaGetSymbolAddress((void**)&k, g_k);
    cudaGetSymbolAddress((void**)&v, g_v);
    cudaGetSymbolAddress((void**)&gate, g_gate);
    cudaGetSymbolAddress((void**)&ckcv, g_ckcv);
    cudaGetSymbolAddress((void**)&outc, g_outc);
    cudaGetSymbolAddress((void**)&selb, g_selb);
    cudaGetSymbolAddress((void**)&attn, g_attn);
    cudaGetSymbolAddress((void**)&mlp, g_mlp);
    cudaGetSymbolAddress((void**)&prt, g_part);

    const int CCN4 = (2 * CM * 64) / 4;
    const int CCRG = (CCN4 + 127) / 128;   // 128-thread blocks
    float* ck = ckcv;
    float* cv = ckcv + (size_t)CM * 64;

    patch_embed_ln_kernel<<<BB * NTOK, 256>>>(img, patch_w, patch_b, pos_emb,
                                              cls_tok, ln1_g, ln1_b, x, h);

    for (int l = 0; l < 2; l++) {
        const float* Wql = Wq + (size_t)l * DIMM * DIMM;
        const float* Wkl = Wk + (size_t)l * DIMM * DIMM;
        const float* Wvl = Wv + (size_t)l * DIMM * DIMM;
        const float* Wgl = Wg + (size_t)l * DIMM * 24;
        const float* Wol = Wo + (size_t)l * DIMM * DIMM;
        const float* kpel = kpe + (size_t)l * 16 * DHH;
        const float* vpel = vpe + (size_t)l * 16 * DHH;
        const float* Wkcl = Wkc + (size_t)l * 1024 * DHH;
        const float* Wvcl = Wvc + (size_t)l * 1024 * DHH;

        qkvgW_kernel<<<dim3(13, 19), 256>>>(h, Wql, Wkl, Wvl, Wgl, q, k, v, gate);

        compress_gemm_kernel<<<dim3((CM + 63) / 64, 2, 8), 256>>>(
            k, v, kpel, vpel, Wkcl, Wvcl, prt);
        reduce8_kernel<<<CCRG, 128>>>(prt, ckcv, CCN4);

        cattn_kernel<<<BB * HH * NQBA, 256>>>(q, ck, cv, outc, selb);
        swc_tile_kernel<<<BB * HH * NQT, 256>>>(q, k, v, outc, gate, selb, attn);

        gemmW_split_kernel<<<dim3(4, 19, 4), 256>>>(attn, Wol, prt, BN, DIMM, DIMM);
        reduce_ln_kernel<<<BN, 128>>>(prt, (const float*)0, x, x,
                                      ln2_g + l * DIMM, ln2_b + l * DIMM, h, 4);

        gemmW_kernel<<<dim3(16, 19), 256>>>(h, ff_w1 + (size_t)l * DIMM * MLPD,
                                            ff_b1 + (size_t)l * MLPD, (const float*)0,
                                            mlp, BN, MLPD, DIMM, ACT_GELU);

        gemmW_split_kernel<<<dim3(4, 19, 4), 256>>>(mlp, ff_w2 + (size_t)l * MLPD * DIMM,
                                                    prt, BN, DIMM, MLPD);
        if (l == 0) {
            reduce_ln_kernel<<<BN, 128>>>(prt, ff_b2, x, x,
                                          ln1_g + DIMM, ln1_b + DIMM, h, 4);
        } else {
            reduce_ln_kernel<<<BN, 128>>>(prt, ff_b2 + (size_t)l * DIMM, x, x,
                                          (const float*)0, (const float*)0, h, 4);
        }
    }

    head_ln_kernel<<<dim3(BB, (NCLS + 255) / 256), 256>>>(
        x, hln_g, hln_b, head_w, head_b, (float*)d_out);
}